// round 11
// baseline (speedup 1.0000x reference)
#include <cuda_runtime.h>
#include <cuda_bf16.h>
#include <math.h>
#include <stdint.h>

#define Bn    4
#define COH   128
#define COW   128
#define CLS   19
#define FIH   256
#define FIW   256
#define FIC   256
#define PTR   8192
#define POS   24576
#define NUNC  6144
#define NRAND 2048
#define NSORT 32768
#define KDIM  275
#define NH    256
#define CHUNK 4096
#define KP2   288        // padded K for tensor path (9 x 32)
#define NC    9          // K chunks
#define MTOT  32768      // Bn*PTR

// ------------------------- scratch (device globals, no allocs) -------------
__device__ unsigned long long g_keys[Bn * NSORT];
__device__ __align__(16) __nv_bfloat16 g_Xa_hi[(size_t)MTOT * KP2];
__device__ __align__(16) __nv_bfloat16 g_Xa_lo[(size_t)MTOT * KP2];
__device__ __align__(16) __nv_bfloat16 g_Xb_hi[(size_t)MTOT * KP2];
__device__ __align__(16) __nv_bfloat16 g_Xb_lo[(size_t)MTOT * KP2];
__device__ __align__(16) __nv_bfloat16 g_Wt_hi[3 * 256 * KP2];
__device__ __align__(16) __nv_bfloat16 g_Wt_lo[3 * 256 * KP2];

// ------------------------- small helpers -----------------------------------
__device__ __forceinline__ float lerp_rn(float w, float a, float b) {
    return __fadd_rn(__fmul_rn(__fsub_rn(1.0f, w), a), __fmul_rn(w, b));
}
__device__ __forceinline__ float bf_hi(float v) {
    return __bfloat162float(__float2bfloat16(v));
}
__device__ __forceinline__ uint32_t packbf(float e0, float e1) {
    uint32_t r;
    asm("cvt.rn.bf16x2.f32 %0, %1, %2;" : "=r"(r) : "f"(e1), "f"(e0));
    return r;
}
__device__ __forceinline__ uint32_t smem_u32(const void* p) {
    uint32_t a;
    asm("{ .reg .u64 t; cvta.to.shared.u64 t, %1; cvt.u32.u64 %0, t; }" : "=r"(a) : "l"(p));
    return a;
}
__device__ __forceinline__ void cp16(uint32_t dst, const void* src) {
    asm volatile("cp.async.cg.shared.global [%0], [%1], 16;" :: "r"(dst), "l"(src) : "memory");
}
__device__ __forceinline__ void cp_commit() {
    asm volatile("cp.async.commit_group;" ::: "memory");
}
template <int N>
__device__ __forceinline__ void cp_wait() {
    asm volatile("cp.async.wait_group %0;" :: "n"(N) : "memory");
}
__device__ __forceinline__ void ldsm4(uint32_t r[4], uint32_t addr) {
    asm volatile("ldmatrix.sync.aligned.m8n8.x4.shared.b16 {%0,%1,%2,%3}, [%4];"
                 : "=r"(r[0]), "=r"(r[1]), "=r"(r[2]), "=r"(r[3]) : "r"(addr));
}
__device__ __forceinline__ void ldsm2(uint32_t r[2], uint32_t addr) {
    asm volatile("ldmatrix.sync.aligned.m8n8.x2.shared.b16 {%0,%1}, [%2];"
                 : "=r"(r[0]), "=r"(r[1]) : "r"(addr));
}
__device__ __forceinline__ void mma_bf16(float c[4], const uint32_t a[4], const uint32_t b[2]) {
    asm volatile(
        "mma.sync.aligned.m16n8k16.row.col.f32.bf16.bf16.f32 "
        "{%0,%1,%2,%3}, {%4,%5,%6,%7}, {%8,%9}, {%0,%1,%2,%3};"
        : "+f"(c[0]), "+f"(c[1]), "+f"(c[2]), "+f"(c[3])
        : "r"(a[0]), "r"(a[1]), "r"(a[2]), "r"(a[3]), "r"(b[0]), "r"(b[1]));
}

// ------------------------- piggyback bodies (1024-thread blocks) -----------
__device__ void body_resize1024(int rblk, const float* __restrict__ coarse,
                                float* __restrict__ op) {
    int t = rblk * 1024 + threadIdx.x;   // pixel id, 0..1048575
    int b = t >> 18;
    int rem = t & 262143;
    int y = rem >> 9;
    int x = rem & 511;
    float sy = (y + 0.5f) * 0.25f - 0.5f;
    float sx = (x + 0.5f) * 0.25f - 0.5f;
    float y0f = floorf(sy), x0f = floorf(sx);
    float wy = sy - y0f, wx = sx - x0f;
    int y0 = min(max((int)y0f, 0), COH - 1);
    int y1 = min(max((int)y0f + 1, 0), COH - 1);
    int x0 = min(max((int)x0f, 0), COW - 1);
    int x1 = min(max((int)x0f + 1, 0), COW - 1);
    const float* cb = coarse + (size_t)b * COH * COW * CLS;
    const float* p00 = cb + (y0 * COW + x0) * CLS;
    const float* p01 = cb + (y0 * COW + x1) * CLS;
    const float* p10 = cb + (y1 * COW + x0) * CLS;
    const float* p11 = cb + (y1 * COW + x1) * CLS;
    float v[CLS];
    float m = -3.0e38f;
#pragma unroll
    for (int c = 0; c < CLS; c++) {
        float top = (1.f - wx) * p00[c] + wx * p01[c];
        float bot = (1.f - wx) * p10[c] + wx * p11[c];
        v[c] = (1.f - wy) * top + wy * bot;
        m = fmaxf(m, v[c]);
    }
    float s = 0.f;
#pragma unroll
    for (int c = 0; c < CLS; c++) {
        v[c] = expf(v[c] - m);
        s += v[c];
    }
    float inv = 1.f / s;
    float* o = op + (size_t)t * CLS;
#pragma unroll
    for (int c = 0; c < CLS; c++) o[c] = v[c] * inv;
}

__device__ void body_prepw1024(int blk, const float* __restrict__ w0,
                               const float* __restrict__ w1, const float* __restrict__ w2) {
    int t = blk * 1024 + threadIdx.x;   // 3*256*288 = 221184 jobs, 216 blocks
    if (t >= 3 * 256 * KP2) return;
    int l = t / (256 * KP2);
    int rem = t - l * 256 * KP2;
    int n = rem / KP2, k = rem - n * KP2;
    const float* W = (l == 0) ? w0 : ((l == 1) ? w1 : w2);
    int r;
    if (l == 0) r = (k < 256) ? (k + CLS) : ((k < KDIM) ? (k - 256) : -1);
    else        r = (k < KDIM) ? k : -1;
    float v = (r >= 0) ? W[(size_t)r * NH + n] : 0.f;
    float h = bf_hi(v);
    g_Wt_hi[t] = __float2bfloat16(v);
    g_Wt_lo[t] = __float2bfloat16(v - h);
}

// ------------------------- 1. uncertainty (bit-exact path) ------------------
__global__ void k_uncertainty(const float* __restrict__ coarse, const float* __restrict__ rc) {
    int t = blockIdx.x * 256 + threadIdx.x;
    int b = t >> 15;
    int p = t & (NSORT - 1);
    if (p >= POS) { g_keys[t] = ~0ull; return; }
    float cy = rc[((size_t)b * POS + p) * 2 + 0];
    float cx = rc[((size_t)b * POS + p) * 2 + 1];
    float y = __fadd_rn(__fmul_rn(cy, 128.f), -0.5f);
    float x = __fadd_rn(__fmul_rn(cx, 128.f), -0.5f);
    float y0f = floorf(y), x0f = floorf(x);
    float wy = __fsub_rn(y, y0f);
    float wx = __fsub_rn(x, x0f);
    int y0 = min(max((int)y0f, 0), COH - 1);
    int y1 = min(max((int)y0f + 1, 0), COH - 1);
    int x0 = min(max((int)x0f, 0), COW - 1);
    int x1 = min(max((int)x0f + 1, 0), COW - 1);
    const float* cb = coarse + (size_t)b * COH * COW * CLS;
    const float* p00 = cb + (y0 * COW + x0) * CLS;
    const float* p01 = cb + (y0 * COW + x1) * CLS;
    const float* p10 = cb + (y1 * COW + x0) * CLS;
    const float* p11 = cb + (y1 * COW + x1) * CLS;
    float m1 = -3.0e38f, m2 = -3.0e38f;
#pragma unroll
    for (int c = 0; c < CLS; c++) {
        float top = lerp_rn(wx, p00[c], p01[c]);
        float bot = lerp_rn(wx, p10[c], p11[c]);
        float v = lerp_rn(wy, top, bot);
        if (v > m1) { m2 = m1; m1 = v; }
        else if (v > m2) m2 = v;
    }
    float unc = __fsub_rn(m2, m1);
    unsigned u = __float_as_uint(unc);
    u = (u & 0x80000000u) ? ~u : (u | 0x80000000u);
    u = ~u;
    g_keys[t] = ((unsigned long long)u << 32) | (unsigned)p;
}

// ------------------------- 2. bitonic sort + piggybacked work ---------------
// blocks [0,32): sort | [32,288): resize pixels 0..255 | [288,504): prep_w
__global__ __launch_bounds__(1024) void k_lsort(const float* __restrict__ coarse,
                                                float* __restrict__ out_probs,
                                                const float* __restrict__ w0,
                                                const float* __restrict__ w1,
                                                const float* __restrict__ w2) {
    __shared__ unsigned long long s[CHUNK];
    if (blockIdx.x >= 32) {
        if (blockIdx.x < 288) body_resize1024(blockIdx.x - 32, coarse, out_probs);
        else body_prepw1024(blockIdx.x - 288, w0, w1, w2);
        return;
    }
    int base = blockIdx.x * CHUNK;
    int lbase = base & (NSORT - 1);
    for (int i = threadIdx.x; i < CHUNK; i += 1024) s[i] = g_keys[base + i];
    __syncthreads();
    for (int k = 2; k <= CHUNK; k <<= 1) {
        for (int j = k >> 1; j >= 64; j >>= 1) {
#pragma unroll
            for (int r = 0; r < 2; r++) {
                int t = threadIdx.x + r * 1024;
                int i = ((t & ~(j - 1)) << 1) | (t & (j - 1));
                int ixj = i + j;
                bool up = (((lbase + i) & k) == 0);
                unsigned long long A = s[i], Bv = s[ixj];
                if ((A > Bv) == up) { s[i] = Bv; s[ixj] = A; }
            }
            __syncthreads();
        }
        int j0 = (k >> 1) < 32 ? (k >> 1) : 32;
        for (int j = j0; j > 0; j >>= 1) {
#pragma unroll
            for (int r = 0; r < 2; r++) {
                int t = threadIdx.x + r * 1024;
                int i = ((t & ~(j - 1)) << 1) | (t & (j - 1));
                int ixj = i + j;
                bool up = (((lbase + i) & k) == 0);
                unsigned long long A = s[i], Bv = s[ixj];
                if ((A > Bv) == up) { s[i] = Bv; s[ixj] = A; }
            }
            __syncwarp();
        }
        __syncthreads();
    }
    for (int i = threadIdx.x; i < CHUNK; i += 1024) g_keys[base + i] = s[i];
}

// column merge + piggybacked resize. blocks [0,32): merge | rest: resize.
__global__ __launch_bounds__(1024) void k_colmerge(int k, int rbase,
                                                   const float* __restrict__ coarse,
                                                   float* __restrict__ out_probs) {
    __shared__ unsigned long long s[CHUNK];
    if (blockIdx.x >= 32) { body_resize1024(rbase + blockIdx.x - 32, coarse, out_probs); return; }
    int b = blockIdx.x >> 3, st = blockIdx.x & 7;
    size_t base = (size_t)b * NSORT + st * 512;
    for (int e = threadIdx.x; e < CHUNK; e += 1024)
        s[e] = g_keys[base + (size_t)(e >> 9) * 4096 + (e & 511)];
    __syncthreads();
    for (int j = k >> 1; j >= 4096; j >>= 1) {
        int jl = j >> 3;
#pragma unroll
        for (int r = 0; r < 2; r++) {
            int t = threadIdx.x + r * 1024;
            int i = ((t & ~(jl - 1)) << 1) | (t & (jl - 1));
            int ixj = i + jl;
            bool up = ((((i >> 9) * 4096) & k) == 0);
            unsigned long long A = s[i], Bv = s[ixj];
            if ((A > Bv) == up) { s[i] = Bv; s[ixj] = A; }
        }
        __syncthreads();
    }
    for (int e = threadIdx.x; e < CHUNK; e += 1024)
        g_keys[base + (size_t)(e >> 9) * 4096 + (e & 511)] = s[e];
}

__device__ __forceinline__ void lmerge_body(int base, int lbase, int k) {
    __shared__ unsigned long long s[CHUNK];
    for (int i = threadIdx.x; i < CHUNK; i += 1024) s[i] = g_keys[base + i];
    __syncthreads();
    for (int j = CHUNK >> 1; j >= 64; j >>= 1) {
#pragma unroll
        for (int r = 0; r < 2; r++) {
            int t = threadIdx.x + r * 1024;
            int i = ((t & ~(j - 1)) << 1) | (t & (j - 1));
            int ixj = i + j;
            bool up = (((lbase + i) & k) == 0);
            unsigned long long A = s[i], Bv = s[ixj];
            if ((A > Bv) == up) { s[i] = Bv; s[ixj] = A; }
        }
        __syncthreads();
    }
    for (int j = 32; j > 0; j >>= 1) {
#pragma unroll
        for (int r = 0; r < 2; r++) {
            int t = threadIdx.x + r * 1024;
            int i = ((t & ~(j - 1)) << 1) | (t & (j - 1));
            int ixj = i + j;
            bool up = (((lbase + i) & k) == 0);
            unsigned long long A = s[i], Bv = s[ixj];
            if ((A > Bv) == up) { s[i] = Bv; s[ixj] = A; }
        }
        __syncwarp();
    }
    __syncthreads();
    for (int i = threadIdx.x; i < CHUNK; i += 1024) g_keys[base + i] = s[i];
}

__global__ __launch_bounds__(1024) void k_lmerge(int k, int rbase,
                                                 const float* __restrict__ coarse,
                                                 float* __restrict__ out_probs) {
    if (blockIdx.x >= 32) { body_resize1024(rbase + blockIdx.x - 32, coarse, out_probs); return; }
    int base = blockIdx.x * CHUNK;
    lmerge_body(base, base & (NSORT - 1), k);
}

__global__ __launch_bounds__(1024) void k_lmerge_top() {
    int b = blockIdx.x >> 1, c = blockIdx.x & 1;
    lmerge_body(b * NSORT + c * CHUNK, c * CHUNK, NSORT);
}

// ------------------------- 4. sampling + coords -> bf16 hi/lo ---------------
__global__ void k_sample(const float* __restrict__ coarse, const float* __restrict__ fine,
                         const float* __restrict__ rc, const float* __restrict__ rf,
                         float* __restrict__ oc) {
    int gt = blockIdx.x * 256 + threadIdx.x;
    int w = gt >> 5, lane = gt & 31;
    int b = w >> 13, p = w & (PTR - 1);
    float cy, cx;
    if (p < NUNC) {
        unsigned idx = (unsigned)(g_keys[(size_t)b * NSORT + p] & 0xffffffffu);
        cy = rc[((size_t)b * POS + idx) * 2 + 0];
        cx = rc[((size_t)b * POS + idx) * 2 + 1];
    } else {
        int q = p - NUNC;
        cy = rf[((size_t)b * NRAND + q) * 2 + 0];
        cx = rf[((size_t)b * NRAND + q) * 2 + 1];
    }
    if (lane == 0) {
        oc[(size_t)w * 2 + 0] = cy;
        oc[(size_t)w * 2 + 1] = cx;
    }
    size_t row = (size_t)w * KP2;

    {   // fine -> cols [0..255] of Xa
        float y = cy * 256.f - 0.5f, x = cx * 256.f - 0.5f;
        float y0f = floorf(y), x0f = floorf(x);
        float wy = y - y0f, wx = x - x0f;
        int y0 = min(max((int)y0f, 0), FIH - 1);
        int y1 = min(max((int)y0f + 1, 0), FIH - 1);
        int x0 = min(max((int)x0f, 0), FIW - 1);
        int x1 = min(max((int)x0f + 1, 0), FIW - 1);
        const float* fb = fine + (size_t)b * FIH * FIW * FIC;
        const float4* f00 = (const float4*)(fb + ((size_t)y0 * FIW + x0) * FIC);
        const float4* f01 = (const float4*)(fb + ((size_t)y0 * FIW + x1) * FIC);
        const float4* f10 = (const float4*)(fb + ((size_t)y1 * FIW + x0) * FIC);
        const float4* f11 = (const float4*)(fb + ((size_t)y1 * FIW + x1) * FIC);
#pragma unroll
        for (int q = 0; q < 2; q++) {
            int c4 = lane + 32 * q;
            float4 a = f00[c4], b2 = f01[c4], c = f10[c4], d = f11[c4];
            float r0 = (1.f - wy) * ((1.f - wx) * a.x + wx * b2.x) + wy * ((1.f - wx) * c.x + wx * d.x);
            float r1 = (1.f - wy) * ((1.f - wx) * a.y + wx * b2.y) + wy * ((1.f - wx) * c.y + wx * d.y);
            float r2 = (1.f - wy) * ((1.f - wx) * a.z + wx * b2.z) + wy * ((1.f - wx) * c.z + wx * d.z);
            float r3 = (1.f - wy) * ((1.f - wx) * a.w + wx * b2.w) + wy * ((1.f - wx) * c.w + wx * d.w);
            uint2 hv, lv;
            hv.x = packbf(r0, r1); hv.y = packbf(r2, r3);
            lv.x = packbf(r0 - bf_hi(r0), r1 - bf_hi(r1));
            lv.y = packbf(r2 - bf_hi(r2), r3 - bf_hi(r3));
            *(uint2*)&g_Xa_hi[row + (size_t)c4 * 4] = hv;
            *(uint2*)&g_Xa_lo[row + (size_t)c4 * 4] = lv;
        }
    }
    {   // coarse residual -> cols [256..287] of Xa AND Xb (zeros past 274)
        float y = cy * 128.f - 0.5f, x = cx * 128.f - 0.5f;
        float y0f = floorf(y), x0f = floorf(x);
        float wy = y - y0f, wx = x - x0f;
        int y0 = min(max((int)y0f, 0), COH - 1);
        int y1 = min(max((int)y0f + 1, 0), COH - 1);
        int x0 = min(max((int)x0f, 0), COW - 1);
        int x1 = min(max((int)x0f + 1, 0), COW - 1);
        const float* cb = coarse + (size_t)b * COH * COW * CLS;
        int c = lane;
        float v = 0.f;
        if (c < CLS) {
            float a = cb[(y0 * COW + x0) * CLS + c];
            float b2 = cb[(y0 * COW + x1) * CLS + c];
            float cc = cb[(y1 * COW + x0) * CLS + c];
            float d = cb[(y1 * COW + x1) * CLS + c];
            v = (1.f - wy) * ((1.f - wx) * a + wx * b2) + wy * ((1.f - wx) * cc + wx * d);
        }
        __nv_bfloat16 hv = __float2bfloat16(v);
        __nv_bfloat16 lv = __float2bfloat16(v - bf_hi(v));
        size_t off = row + 256 + lane;
        g_Xa_hi[off] = hv; g_Xa_lo[off] = lv;
        g_Xb_hi[off] = hv; g_Xb_lo[off] = lv;
    }
}

// ------------------------- 5. HMMA GEMM (bf16 hi/lo split, R5 config) ------
#define PADK 40                      // smem row stride in bf16 (80 B)
#define ABYTES (128 * PADK * 2)      // 10240
#define BUFB   (4 * ABYTES)          // hi/lo x A/B per stage = 40960
#define SM_DYN (3 * BUFB)            // 122880 (3-stage pipeline)
#define RSTR   272                   // epilogue staging row stride (bytes)

__global__ __launch_bounds__(256) void k_gemm_mma(
    const __nv_bfloat16* __restrict__ Xhi, const __nv_bfloat16* __restrict__ Xlo,
    const __nv_bfloat16* __restrict__ Whi, const __nv_bfloat16* __restrict__ Wlo,
    const float* __restrict__ bias,
    __nv_bfloat16* __restrict__ Yhi, __nv_bfloat16* __restrict__ Ylo) {
    extern __shared__ char smem[];
    __shared__ float sbias[128];
    uint32_t sb = smem_u32(smem);
    int tid = threadIdx.x, wid = tid >> 5, lane = tid & 31;
    int wm = wid & 1, wn = wid >> 1;           // warp grid 2 (M) x 4 (N)
    int m0 = (blockIdx.x >> 1) * 128;
    int n0 = (blockIdx.x & 1) * 128;

    if (tid < 128) sbias[tid] = bias[n0 + tid];

    float acc[4][4][4];
#pragma unroll
    for (int i = 0; i < 4; i++)
#pragma unroll
        for (int j = 0; j < 4; j++)
#pragma unroll
            for (int q = 0; q < 4; q++) acc[i][j][q] = 0.f;

    int lrow = tid >> 2;
    int lq = tid & 3;

    auto issue = [&](int c, int buf) {
        int kb = c * 32;
        uint32_t s0 = sb + buf * BUFB;
#pragma unroll
        for (int r = 0; r < 2; r++) {
            int row = lrow + r * 64;
            size_t gA = (size_t)(m0 + row) * KP2 + kb + lq * 8;
            size_t gB = (size_t)(n0 + row) * KP2 + kb + lq * 8;
            uint32_t soff = row * (PADK * 2) + lq * 16;
            cp16(s0 + soff, Xhi + gA);
            cp16(s0 + ABYTES + soff, Xlo + gA);
            cp16(s0 + 2 * ABYTES + soff, Whi + gB);
            cp16(s0 + 3 * ABYTES + soff, Wlo + gB);
        }
        cp_commit();
    };

    issue(0, 0);
    issue(1, 1);

    for (int c = 0; c < NC; c++) {
        if (c <= NC - 3) { issue(c + 2, (c + 2) % 3); cp_wait<2>(); }
        else if (c == NC - 2) cp_wait<1>();
        else cp_wait<0>();
        __syncthreads();
        uint32_t s0 = sb + (c % 3) * BUFB;
#pragma unroll
        for (int k16 = 0; k16 < 2; k16++) {
            uint32_t ah[4][4], al[4][4], bh[4][2], bl[4][2];
            int ka = k16 * 32 + ((lane >> 4) << 4);
            int kb2 = k16 * 32 + (((lane >> 3) & 1) << 4);
#pragma unroll
            for (int mt = 0; mt < 4; mt++) {
                int row = wm * 64 + mt * 16 + (lane & 15);
                uint32_t a = s0 + row * (PADK * 2) + ka;
                ldsm4(ah[mt], a);
                ldsm4(al[mt], a + ABYTES);
            }
#pragma unroll
            for (int nt = 0; nt < 4; nt++) {
                int n = wn * 32 + nt * 8 + (lane & 7);
                uint32_t a = s0 + 2 * ABYTES + n * (PADK * 2) + kb2;
                ldsm2(bh[nt], a);
                ldsm2(bl[nt], a + ABYTES);
            }
#pragma unroll
            for (int mt = 0; mt < 4; mt++)
#pragma unroll
                for (int nt = 0; nt < 4; nt++) {
                    mma_bf16(acc[mt][nt], ah[mt], bh[nt]);
                    mma_bf16(acc[mt][nt], ah[mt], bl[nt]);
                    mma_bf16(acc[mt][nt], al[mt], bh[nt]);
                }
        }
        __syncthreads();
    }

    // epilogue: bias + relu, stage in smem, coalesced uint4 stores (hi then lo)
#pragma unroll
    for (int pass = 0; pass < 2; pass++) {
        __syncthreads();
#pragma unroll
        for (int mt = 0; mt < 4; mt++)
#pragma unroll
            for (int nt = 0; nt < 4; nt++) {
                int col = wn * 32 + nt * 8 + (lane & 3) * 2;
                float bi0 = sbias[col], bi1 = sbias[col + 1];
#pragma unroll
                for (int h = 0; h < 2; h++) {
                    int row = wm * 64 + mt * 16 + (lane >> 2) + h * 8;
                    float v0 = acc[mt][nt][2 * h] + bi0;
                    float v1 = acc[mt][nt][2 * h + 1] + bi1;
                    v0 = v0 > 0.f ? v0 : 0.f;
                    v1 = v1 > 0.f ? v1 : 0.f;
                    uint32_t pv = (pass == 0)
                        ? packbf(v0, v1)
                        : packbf(v0 - bf_hi(v0), v1 - bf_hi(v1));
                    *(uint32_t*)(smem + row * RSTR + col * 2) = pv;
                }
            }
        __syncthreads();
        __nv_bfloat16* Y = (pass == 0) ? Yhi : Ylo;
#pragma unroll
        for (int i = 0; i < 8; i++) {
            int u = tid + i * 256;
            int row = u >> 4, q = u & 15;
            uint4 v = *(uint4*)(smem + row * RSTR + q * 16);
            *(uint4*)&Y[(size_t)(m0 + row) * KP2 + n0 + q * 8] = v;
        }
    }
}

// ------------------------- 6. final layer (N=19) ---------------------------
__global__ __launch_bounds__(256) void k_final(const __nv_bfloat16* __restrict__ Xhi,
                                               const __nv_bfloat16* __restrict__ Xlo,
                                               const float* __restrict__ wf,
                                               const float* __restrict__ bf,
                                               float* __restrict__ out) {
    __shared__ float swf[KDIM * CLS];
    for (int i = threadIdx.x; i < KDIM * CLS; i += 256) swf[i] = wf[i];
    __syncthreads();
    int w = (blockIdx.x * 256 + threadIdx.x) >> 5;
    int lane = threadIdx.x & 31;
    const __nv_bfloat16* xh = Xhi + (size_t)w * KP2;
    const __nv_bfloat16* xl = Xlo + (size_t)w * KP2;
    float acc[CLS];
#pragma unroll
    for (int c = 0; c < CLS; c++) acc[c] = 0.f;
    for (int k = lane; k < KDIM; k += 32) {
        float xv = __bfloat162float(xh[k]) + __bfloat162float(xl[k]);
        const float* wr = &swf[k * CLS];
#pragma unroll
        for (int c = 0; c < CLS; c++) acc[c] += xv * wr[c];
    }
#pragma unroll
    for (int off = 16; off; off >>= 1)
#pragma unroll
        for (int c = 0; c < CLS; c++) acc[c] += __shfl_xor_sync(0xffffffffu, acc[c], off);
    if (lane == 0) {
        float* o = out + (size_t)w * CLS;
#pragma unroll
        for (int c = 0; c < CLS; c++) o[c] = acc[c] + bf[c];
    }
}

// ------------------------- launch ------------------------------------------
extern "C" void kernel_launch(void* const* d_in, const int* in_sizes, int n_in, void* d_out,
                              int out_size) {
    const float* coarse = (const float*)d_in[1];
    const float* fine0 = (const float*)d_in[2];
    const float* rand_coords = (const float*)d_in[3];
    const float* rand_fill = (const float*)d_in[4];
    const float* w0 = (const float*)d_in[5];
    const float* b0 = (const float*)d_in[6];
    const float* w1 = (const float*)d_in[7];
    const float* b1 = (const float*)d_in[8];
    const float* w2 = (const float*)d_in[9];
    const float* b2 = (const float*)d_in[10];
    const float* wf = (const float*)d_in[11];
    const float* bf = (const float*)d_in[12];
    float* out = (float*)d_out;

    const size_t PROBS = (size_t)Bn * 512 * 512 * CLS;
    const size_t LOGITS = (size_t)Bn * PTR * CLS;
    float* out_probs = out;
    float* out_logits = out + PROBS;
    float* out_coords = out + PROBS + LOGITS;

    void *pXah, *pXal, *pXbh, *pXbl, *pWh, *pWl;
    cudaGetSymbolAddress(&pXah, g_Xa_hi);
    cudaGetSymbolAddress(&pXal, g_Xa_lo);
    cudaGetSymbolAddress(&pXbh, g_Xb_hi);
    cudaGetSymbolAddress(&pXbl, g_Xb_lo);
    cudaGetSymbolAddress(&pWh, g_Wt_hi);
    cudaGetSymbolAddress(&pWl, g_Wt_lo);
    __nv_bfloat16* Xah = (__nv_bfloat16*)pXah;
    __nv_bfloat16* Xal = (__nv_bfloat16*)pXal;
    __nv_bfloat16* Xbh = (__nv_bfloat16*)pXbh;
    __nv_bfloat16* Xbl = (__nv_bfloat16*)pXbl;
    __nv_bfloat16* Wh = (__nv_bfloat16*)pWh;
    __nv_bfloat16* Wl = (__nv_bfloat16*)pWl;

    cudaFuncSetAttribute(k_gemm_mma, cudaFuncAttributeMaxDynamicSharedMemorySize, SM_DYN);

    // minimal pre-sort work: uncertainty only
    k_uncertainty<<<512, 256>>>(coarse, rand_coords);

    // sort chain with piggybacked resize_softmax (1024 blocks) + prep_w (216)
    k_lsort<<<504, 1024>>>(coarse, out_probs, w0, w1, w2);
    k_colmerge<<<224, 1024>>>(8192, 256, coarse, out_probs);
    k_lmerge<<<224, 1024>>>(8192, 448, coarse, out_probs);
    k_colmerge<<<160, 1024>>>(16384, 640, coarse, out_probs);
    k_lmerge<<<160, 1024>>>(16384, 768, coarse, out_probs);
    k_colmerge<<<160, 1024>>>(32768, 896, coarse, out_probs);
    k_lmerge_top<<<8, 1024>>>();

    k_sample<<<4096, 256>>>(coarse, fine0, rand_coords, rand_fill, out_coords);

    const int WSTR = 256 * KP2;
    k_gemm_mma<<<512, 256, SM_DYN>>>(Xah, Xal, Wh, Wl, b0, Xbh, Xbl);
    k_gemm_mma<<<512, 256, SM_DYN>>>(Xbh, Xbl, Wh + WSTR, Wl + WSTR, b1, Xah, Xal);
    k_gemm_mma<<<512, 256, SM_DYN>>>(Xah, Xal, Wh + 2 * WSTR, Wl + 2 * WSTR, b2, Xbh, Xbl);
    k_final<<<4096, 256>>>(Xbh, Xbl, wf, bf, out_logits);
}

// round 12
// speedup vs baseline: 1.0235x; 1.0235x over previous
#include <cuda_runtime.h>
#include <cuda_bf16.h>
#include <math.h>
#include <stdint.h>

#define Bn    4
#define COH   128
#define COW   128
#define CLS   19
#define FIH   256
#define FIW   256
#define FIC   256
#define PTR   8192
#define POS   24576
#define NUNC  6144
#define NRAND 2048
#define NSORT 32768
#define KDIM  275
#define NH    256
#define CHUNK 4096
#define KP2   288        // padded K for tensor path (9 x 32)
#define NC    9          // K chunks
#define MTOT  32768      // Bn*PTR

// ------------------------- scratch (device globals, no allocs) -------------
__device__ unsigned long long g_keys[Bn * NSORT];
__device__ __align__(16) __nv_bfloat16 g_Xa_hi[(size_t)MTOT * KP2];
__device__ __align__(16) __nv_bfloat16 g_Xa_lo[(size_t)MTOT * KP2];
__device__ __align__(16) __nv_bfloat16 g_Xb_hi[(size_t)MTOT * KP2];
__device__ __align__(16) __nv_bfloat16 g_Xb_lo[(size_t)MTOT * KP2];
__device__ __align__(16) __nv_bfloat16 g_Wt_hi[3 * 256 * KP2];
__device__ __align__(16) __nv_bfloat16 g_Wt_lo[3 * 256 * KP2];

// ------------------------- small helpers -----------------------------------
__device__ __forceinline__ float lerp_rn(float w, float a, float b) {
    return __fadd_rn(__fmul_rn(__fsub_rn(1.0f, w), a), __fmul_rn(w, b));
}
__device__ __forceinline__ float bf_hi(float v) {
    return __bfloat162float(__float2bfloat16(v));
}
__device__ __forceinline__ uint32_t packbf(float e0, float e1) {
    uint32_t r;
    asm("cvt.rn.bf16x2.f32 %0, %1, %2;" : "=r"(r) : "f"(e1), "f"(e0));
    return r;
}
__device__ __forceinline__ uint32_t smem_u32(const void* p) {
    uint32_t a;
    asm("{ .reg .u64 t; cvta.to.shared.u64 t, %1; cvt.u32.u64 %0, t; }" : "=r"(a) : "l"(p));
    return a;
}
__device__ __forceinline__ void cp16(uint32_t dst, const void* src) {
    asm volatile("cp.async.cg.shared.global [%0], [%1], 16;" :: "r"(dst), "l"(src) : "memory");
}
__device__ __forceinline__ void cp_commit() {
    asm volatile("cp.async.commit_group;" ::: "memory");
}
template <int N>
__device__ __forceinline__ void cp_wait() {
    asm volatile("cp.async.wait_group %0;" :: "n"(N) : "memory");
}
__device__ __forceinline__ void ldsm4(uint32_t r[4], uint32_t addr) {
    asm volatile("ldmatrix.sync.aligned.m8n8.x4.shared.b16 {%0,%1,%2,%3}, [%4];"
                 : "=r"(r[0]), "=r"(r[1]), "=r"(r[2]), "=r"(r[3]) : "r"(addr));
}
__device__ __forceinline__ void ldsm2(uint32_t r[2], uint32_t addr) {
    asm volatile("ldmatrix.sync.aligned.m8n8.x2.shared.b16 {%0,%1}, [%2];"
                 : "=r"(r[0]), "=r"(r[1]) : "r"(addr));
}
__device__ __forceinline__ void mma_bf16(float c[4], const uint32_t a[4], const uint32_t b[2]) {
    asm volatile(
        "mma.sync.aligned.m16n8k16.row.col.f32.bf16.bf16.f32 "
        "{%0,%1,%2,%3}, {%4,%5,%6,%7}, {%8,%9}, {%0,%1,%2,%3};"
        : "+f"(c[0]), "+f"(c[1]), "+f"(c[2]), "+f"(c[3])
        : "r"(a[0]), "r"(a[1]), "r"(a[2]), "r"(a[3]), "r"(b[0]), "r"(b[1]));
}

// ------------------------- setup bodies (fused into one kernel) -------------
__device__ void body_resize_softmax(int blk, const float* __restrict__ coarse,
                                    float* __restrict__ op) {
    int t = blk * 256 + threadIdx.x;
    int b = t >> 18;
    int rem = t & 262143;
    int y = rem >> 9;
    int x = rem & 511;
    float sy = (y + 0.5f) * 0.25f - 0.5f;
    float sx = (x + 0.5f) * 0.25f - 0.5f;
    float y0f = floorf(sy), x0f = floorf(sx);
    float wy = sy - y0f, wx = sx - x0f;
    int y0 = min(max((int)y0f, 0), COH - 1);
    int y1 = min(max((int)y0f + 1, 0), COH - 1);
    int x0 = min(max((int)x0f, 0), COW - 1);
    int x1 = min(max((int)x0f + 1, 0), COW - 1);
    const float* cb = coarse + (size_t)b * COH * COW * CLS;
    const float* p00 = cb + (y0 * COW + x0) * CLS;
    const float* p01 = cb + (y0 * COW + x1) * CLS;
    const float* p10 = cb + (y1 * COW + x0) * CLS;
    const float* p11 = cb + (y1 * COW + x1) * CLS;
    float v[CLS];
    float m = -3.0e38f;
#pragma unroll
    for (int c = 0; c < CLS; c++) {
        float top = (1.f - wx) * p00[c] + wx * p01[c];
        float bot = (1.f - wx) * p10[c] + wx * p11[c];
        v[c] = (1.f - wy) * top + wy * bot;
        m = fmaxf(m, v[c]);
    }
    float s = 0.f;
#pragma unroll
    for (int c = 0; c < CLS; c++) {
        v[c] = expf(v[c] - m);
        s += v[c];
    }
    float inv = 1.f / s;
    float* o = op + (size_t)t * CLS;
#pragma unroll
    for (int c = 0; c < CLS; c++) o[c] = v[c] * inv;
}

__device__ void body_prep_w(int blk, const float* __restrict__ w0,
                            const float* __restrict__ w1, const float* __restrict__ w2) {
    int t = blk * 256 + threadIdx.x;   // 3*256*288
    if (t >= 3 * 256 * KP2) return;
    int l = t / (256 * KP2);
    int rem = t - l * 256 * KP2;
    int n = rem / KP2, k = rem - n * KP2;
    const float* W = (l == 0) ? w0 : ((l == 1) ? w1 : w2);
    int r;
    if (l == 0) r = (k < 256) ? (k + CLS) : ((k < KDIM) ? (k - 256) : -1);
    else        r = (k < KDIM) ? k : -1;
    float v = (r >= 0) ? W[(size_t)r * NH + n] : 0.f;
    float h = bf_hi(v);
    g_Wt_hi[t] = __float2bfloat16(v);
    g_Wt_lo[t] = __float2bfloat16(v - h);
}

__device__ void body_uncertainty(int blk, const float* __restrict__ coarse,
                                 const float* __restrict__ rc) {
    int t = blk * 256 + threadIdx.x;
    int b = t >> 15;
    int p = t & (NSORT - 1);
    if (p >= POS) { g_keys[t] = ~0ull; return; }
    float cy = rc[((size_t)b * POS + p) * 2 + 0];
    float cx = rc[((size_t)b * POS + p) * 2 + 1];
    float y = __fadd_rn(__fmul_rn(cy, 128.f), -0.5f);
    float x = __fadd_rn(__fmul_rn(cx, 128.f), -0.5f);
    float y0f = floorf(y), x0f = floorf(x);
    float wy = __fsub_rn(y, y0f);
    float wx = __fsub_rn(x, x0f);
    int y0 = min(max((int)y0f, 0), COH - 1);
    int y1 = min(max((int)y0f + 1, 0), COH - 1);
    int x0 = min(max((int)x0f, 0), COW - 1);
    int x1 = min(max((int)x0f + 1, 0), COW - 1);
    const float* cb = coarse + (size_t)b * COH * COW * CLS;
    const float* p00 = cb + (y0 * COW + x0) * CLS;
    const float* p01 = cb + (y0 * COW + x1) * CLS;
    const float* p10 = cb + (y1 * COW + x0) * CLS;
    const float* p11 = cb + (y1 * COW + x1) * CLS;
    float m1 = -3.0e38f, m2 = -3.0e38f;
#pragma unroll
    for (int c = 0; c < CLS; c++) {
        float top = lerp_rn(wx, p00[c], p01[c]);
        float bot = lerp_rn(wx, p10[c], p11[c]);
        float v = lerp_rn(wy, top, bot);
        if (v > m1) { m2 = m1; m1 = v; }
        else if (v > m2) m2 = v;
    }
    float unc = __fsub_rn(m2, m1);
    unsigned u = __float_as_uint(unc);
    u = (u & 0x80000000u) ? ~u : (u | 0x80000000u);
    u = ~u;
    g_keys[t] = ((unsigned long long)u << 32) | (unsigned)p;
}

// one launch: blocks [0,4096) resize | [4096,4960) prep_w | [4960,5472) unc
__global__ __launch_bounds__(256) void k_setup(const float* __restrict__ coarse,
                                               const float* __restrict__ rc,
                                               const float* __restrict__ w0,
                                               const float* __restrict__ w1,
                                               const float* __restrict__ w2,
                                               float* __restrict__ out_probs) {
    int blk = blockIdx.x;
    if (blk < 4096) body_resize_softmax(blk, coarse, out_probs);
    else if (blk < 4960) body_prep_w(blk - 4096, w0, w1, w2);
    else body_uncertainty(blk - 4960, coarse, rc);
}

// ------------------------- 2. bitonic sort ---------------------------------
__global__ __launch_bounds__(1024) void k_lsort() {
    __shared__ unsigned long long s[CHUNK];
    int base = blockIdx.x * CHUNK;
    int lbase = base & (NSORT - 1);
    for (int i = threadIdx.x; i < CHUNK; i += 1024) s[i] = g_keys[base + i];
    __syncthreads();
    for (int k = 2; k <= CHUNK; k <<= 1) {
        for (int j = k >> 1; j >= 64; j >>= 1) {
#pragma unroll
            for (int r = 0; r < 2; r++) {
                int t = threadIdx.x + r * 1024;
                int i = ((t & ~(j - 1)) << 1) | (t & (j - 1));
                int ixj = i + j;
                bool up = (((lbase + i) & k) == 0);
                unsigned long long A = s[i], Bv = s[ixj];
                if ((A > Bv) == up) { s[i] = Bv; s[ixj] = A; }
            }
            __syncthreads();
        }
        int j0 = (k >> 1) < 32 ? (k >> 1) : 32;
        for (int j = j0; j > 0; j >>= 1) {
#pragma unroll
            for (int r = 0; r < 2; r++) {
                int t = threadIdx.x + r * 1024;
                int i = ((t & ~(j - 1)) << 1) | (t & (j - 1));
                int ixj = i + j;
                bool up = (((lbase + i) & k) == 0);
                unsigned long long A = s[i], Bv = s[ixj];
                if ((A > Bv) == up) { s[i] = Bv; s[ixj] = A; }
            }
            __syncwarp();
        }
        __syncthreads();
    }
    for (int i = threadIdx.x; i < CHUNK; i += 1024) g_keys[base + i] = s[i];
}

// column merge: all global passes (j >= 4096) of stage k in one smem residency.
__global__ __launch_bounds__(1024) void k_colmerge(int k) {
    __shared__ unsigned long long s[CHUNK];
    int b = blockIdx.x >> 3, st = blockIdx.x & 7;
    size_t base = (size_t)b * NSORT + st * 512;
    for (int e = threadIdx.x; e < CHUNK; e += 1024)
        s[e] = g_keys[base + (size_t)(e >> 9) * 4096 + (e & 511)];
    __syncthreads();
    for (int j = k >> 1; j >= 4096; j >>= 1) {
        int jl = j >> 3;
#pragma unroll
        for (int r = 0; r < 2; r++) {
            int t = threadIdx.x + r * 1024;
            int i = ((t & ~(jl - 1)) << 1) | (t & (jl - 1));
            int ixj = i + jl;
            bool up = ((((i >> 9) * 4096) & k) == 0);
            unsigned long long A = s[i], Bv = s[ixj];
            if ((A > Bv) == up) { s[i] = Bv; s[ixj] = A; }
        }
        __syncthreads();
    }
    for (int e = threadIdx.x; e < CHUNK; e += 1024)
        g_keys[base + (size_t)(e >> 9) * 4096 + (e & 511)] = s[e];
}

__device__ __forceinline__ void lmerge_body(int base, int lbase, int k) {
    __shared__ unsigned long long s[CHUNK];
    for (int i = threadIdx.x; i < CHUNK; i += 1024) s[i] = g_keys[base + i];
    __syncthreads();
    for (int j = CHUNK >> 1; j >= 64; j >>= 1) {
#pragma unroll
        for (int r = 0; r < 2; r++) {
            int t = threadIdx.x + r * 1024;
            int i = ((t & ~(j - 1)) << 1) | (t & (j - 1));
            int ixj = i + j;
            bool up = (((lbase + i) & k) == 0);
            unsigned long long A = s[i], Bv = s[ixj];
            if ((A > Bv) == up) { s[i] = Bv; s[ixj] = A; }
        }
        __syncthreads();
    }
    for (int j = 32; j > 0; j >>= 1) {
#pragma unroll
        for (int r = 0; r < 2; r++) {
            int t = threadIdx.x + r * 1024;
            int i = ((t & ~(j - 1)) << 1) | (t & (j - 1));
            int ixj = i + j;
            bool up = (((lbase + i) & k) == 0);
            unsigned long long A = s[i], Bv = s[ixj];
            if ((A > Bv) == up) { s[i] = Bv; s[ixj] = A; }
        }
        __syncwarp();
    }
    __syncthreads();
    for (int i = threadIdx.x; i < CHUNK; i += 1024) g_keys[base + i] = s[i];
}

__global__ __launch_bounds__(1024) void k_lmerge(int k) {
    int base = blockIdx.x * CHUNK;
    lmerge_body(base, base & (NSORT - 1), k);
}

__global__ __launch_bounds__(1024) void k_lmerge_top() {
    int b = blockIdx.x >> 1, c = blockIdx.x & 1;
    lmerge_body(b * NSORT + c * CHUNK, c * CHUNK, NSORT);
}

// ------------------------- 4. sampling + coords -> bf16 hi/lo ---------------
__global__ void k_sample(const float* __restrict__ coarse, const float* __restrict__ fine,
                         const float* __restrict__ rc, const float* __restrict__ rf,
                         float* __restrict__ oc) {
    int gt = blockIdx.x * 256 + threadIdx.x;
    int w = gt >> 5, lane = gt & 31;
    int b = w >> 13, p = w & (PTR - 1);
    float cy, cx;
    if (p < NUNC) {
        unsigned idx = (unsigned)(g_keys[(size_t)b * NSORT + p] & 0xffffffffu);
        cy = rc[((size_t)b * POS + idx) * 2 + 0];
        cx = rc[((size_t)b * POS + idx) * 2 + 1];
    } else {
        int q = p - NUNC;
        cy = rf[((size_t)b * NRAND + q) * 2 + 0];
        cx = rf[((size_t)b * NRAND + q) * 2 + 1];
    }
    if (lane == 0) {
        oc[(size_t)w * 2 + 0] = cy;
        oc[(size_t)w * 2 + 1] = cx;
    }
    size_t row = (size_t)w * KP2;

    {   // fine -> cols [0..255] of Xa
        float y = cy * 256.f - 0.5f, x = cx * 256.f - 0.5f;
        float y0f = floorf(y), x0f = floorf(x);
        float wy = y - y0f, wx = x - x0f;
        int y0 = min(max((int)y0f, 0), FIH - 1);
        int y1 = min(max((int)y0f + 1, 0), FIH - 1);
        int x0 = min(max((int)x0f, 0), FIW - 1);
        int x1 = min(max((int)x0f + 1, 0), FIW - 1);
        const float* fb = fine + (size_t)b * FIH * FIW * FIC;
        const float4* f00 = (const float4*)(fb + ((size_t)y0 * FIW + x0) * FIC);
        const float4* f01 = (const float4*)(fb + ((size_t)y0 * FIW + x1) * FIC);
        const float4* f10 = (const float4*)(fb + ((size_t)y1 * FIW + x0) * FIC);
        const float4* f11 = (const float4*)(fb + ((size_t)y1 * FIW + x1) * FIC);
#pragma unroll
        for (int q = 0; q < 2; q++) {
            int c4 = lane + 32 * q;
            float4 a = f00[c4], b2 = f01[c4], c = f10[c4], d = f11[c4];
            float r0 = (1.f - wy) * ((1.f - wx) * a.x + wx * b2.x) + wy * ((1.f - wx) * c.x + wx * d.x);
            float r1 = (1.f - wy) * ((1.f - wx) * a.y + wx * b2.y) + wy * ((1.f - wx) * c.y + wx * d.y);
            float r2 = (1.f - wy) * ((1.f - wx) * a.z + wx * b2.z) + wy * ((1.f - wx) * c.z + wx * d.z);
            float r3 = (1.f - wy) * ((1.f - wx) * a.w + wx * b2.w) + wy * ((1.f - wx) * c.w + wx * d.w);
            uint2 hv, lv;
            hv.x = packbf(r0, r1); hv.y = packbf(r2, r3);
            lv.x = packbf(r0 - bf_hi(r0), r1 - bf_hi(r1));
            lv.y = packbf(r2 - bf_hi(r2), r3 - bf_hi(r3));
            *(uint2*)&g_Xa_hi[row + (size_t)c4 * 4] = hv;
            *(uint2*)&g_Xa_lo[row + (size_t)c4 * 4] = lv;
        }
    }
    {   // coarse residual -> cols [256..287] of Xa AND Xb (zeros past 274)
        float y = cy * 128.f - 0.5f, x = cx * 128.f - 0.5f;
        float y0f = floorf(y), x0f = floorf(x);
        float wy = y - y0f, wx = x - x0f;
        int y0 = min(max((int)y0f, 0), COH - 1);
        int y1 = min(max((int)y0f + 1, 0), COH - 1);
        int x0 = min(max((int)x0f, 0), COW - 1);
        int x1 = min(max((int)x0f + 1, 0), COW - 1);
        const float* cb = coarse + (size_t)b * COH * COW * CLS;
        int c = lane;
        float v = 0.f;
        if (c < CLS) {
            float a = cb[(y0 * COW + x0) * CLS + c];
            float b2 = cb[(y0 * COW + x1) * CLS + c];
            float cc = cb[(y1 * COW + x0) * CLS + c];
            float d = cb[(y1 * COW + x1) * CLS + c];
            v = (1.f - wy) * ((1.f - wx) * a + wx * b2) + wy * ((1.f - wx) * cc + wx * d);
        }
        __nv_bfloat16 hv = __float2bfloat16(v);
        __nv_bfloat16 lv = __float2bfloat16(v - bf_hi(v));
        size_t off = row + 256 + lane;
        g_Xa_hi[off] = hv; g_Xa_lo[off] = lv;
        g_Xb_hi[off] = hv; g_Xb_lo[off] = lv;
    }
}

// ------------------------- 5. HMMA GEMM (bf16 hi/lo split, R5 config) ------
#define PADK 40                      // smem row stride in bf16 (80 B)
#define ABYTES (128 * PADK * 2)      // 10240
#define BUFB   (4 * ABYTES)          // hi/lo x A/B per stage = 40960
#define SM_DYN (3 * BUFB)            // 122880 (3-stage pipeline)
#define RSTR   272                   // epilogue staging row stride (bytes)

__global__ __launch_bounds__(256) void k_gemm_mma(
    const __nv_bfloat16* __restrict__ Xhi, const __nv_bfloat16* __restrict__ Xlo,
    const __nv_bfloat16* __restrict__ Whi, const __nv_bfloat16* __restrict__ Wlo,
    const float* __restrict__ bias,
    __nv_bfloat16* __restrict__ Yhi, __nv_bfloat16* __restrict__ Ylo) {
    extern __shared__ char smem[];
    __shared__ float sbias[128];
    uint32_t sb = smem_u32(smem);
    int tid = threadIdx.x, wid = tid >> 5, lane = tid & 31;
    int wm = wid & 1, wn = wid >> 1;           // warp grid 2 (M) x 4 (N)
    int m0 = (blockIdx.x >> 1) * 128;
    int n0 = (blockIdx.x & 1) * 128;

    if (tid < 128) sbias[tid] = bias[n0 + tid];

    float acc[4][4][4];
#pragma unroll
    for (int i = 0; i < 4; i++)
#pragma unroll
        for (int j = 0; j < 4; j++)
#pragma unroll
            for (int q = 0; q < 4; q++) acc[i][j][q] = 0.f;

    int lrow = tid >> 2;
    int lq = tid & 3;

    auto issue = [&](int c, int buf) {
        int kb = c * 32;
        uint32_t s0 = sb + buf * BUFB;
#pragma unroll
        for (int r = 0; r < 2; r++) {
            int row = lrow + r * 64;
            size_t gA = (size_t)(m0 + row) * KP2 + kb + lq * 8;
            size_t gB = (size_t)(n0 + row) * KP2 + kb + lq * 8;
            uint32_t soff = row * (PADK * 2) + lq * 16;
            cp16(s0 + soff, Xhi + gA);
            cp16(s0 + ABYTES + soff, Xlo + gA);
            cp16(s0 + 2 * ABYTES + soff, Whi + gB);
            cp16(s0 + 3 * ABYTES + soff, Wlo + gB);
        }
        cp_commit();
    };

    issue(0, 0);
    issue(1, 1);

    for (int c = 0; c < NC; c++) {
        if (c <= NC - 3) { issue(c + 2, (c + 2) % 3); cp_wait<2>(); }
        else if (c == NC - 2) cp_wait<1>();
        else cp_wait<0>();
        __syncthreads();
        uint32_t s0 = sb + (c % 3) * BUFB;
#pragma unroll
        for (int k16 = 0; k16 < 2; k16++) {
            uint32_t ah[4][4], al[4][4], bh[4][2], bl[4][2];
            int ka = k16 * 32 + ((lane >> 4) << 4);
            int kb2 = k16 * 32 + (((lane >> 3) & 1) << 4);
#pragma unroll
            for (int mt = 0; mt < 4; mt++) {
                int row = wm * 64 + mt * 16 + (lane & 15);
                uint32_t a = s0 + row * (PADK * 2) + ka;
                ldsm4(ah[mt], a);
                ldsm4(al[mt], a + ABYTES);
            }
#pragma unroll
            for (int nt = 0; nt < 4; nt++) {
                int n = wn * 32 + nt * 8 + (lane & 7);
                uint32_t a = s0 + 2 * ABYTES + n * (PADK * 2) + kb2;
                ldsm2(bh[nt], a);
                ldsm2(bl[nt], a + ABYTES);
            }
#pragma unroll
            for (int mt = 0; mt < 4; mt++)
#pragma unroll
                for (int nt = 0; nt < 4; nt++) {
                    mma_bf16(acc[mt][nt], ah[mt], bh[nt]);
                    mma_bf16(acc[mt][nt], ah[mt], bl[nt]);
                    mma_bf16(acc[mt][nt], al[mt], bh[nt]);
                }
        }
        __syncthreads();
    }

    // epilogue: bias + relu, stage in smem, coalesced uint4 stores (hi then lo)
#pragma unroll
    for (int pass = 0; pass < 2; pass++) {
        __syncthreads();
#pragma unroll
        for (int mt = 0; mt < 4; mt++)
#pragma unroll
            for (int nt = 0; nt < 4; nt++) {
                int col = wn * 32 + nt * 8 + (lane & 3) * 2;
                float bi0 = sbias[col], bi1 = sbias[col + 1];
#pragma unroll
                for (int h = 0; h < 2; h++) {
                    int row = wm * 64 + mt * 16 + (lane >> 2) + h * 8;
                    float v0 = acc[mt][nt][2 * h] + bi0;
                    float v1 = acc[mt][nt][2 * h + 1] + bi1;
                    v0 = v0 > 0.f ? v0 : 0.f;
                    v1 = v1 > 0.f ? v1 : 0.f;
                    uint32_t pv = (pass == 0)
                        ? packbf(v0, v1)
                        : packbf(v0 - bf_hi(v0), v1 - bf_hi(v1));
                    *(uint32_t*)(smem + row * RSTR + col * 2) = pv;
                }
            }
        __syncthreads();
        __nv_bfloat16* Y = (pass == 0) ? Yhi : Ylo;
#pragma unroll
        for (int i = 0; i < 8; i++) {
            int u = tid + i * 256;
            int row = u >> 4, q = u & 15;
            uint4 v = *(uint4*)(smem + row * RSTR + q * 16);
            *(uint4*)&Y[(size_t)(m0 + row) * KP2 + n0 + q * 8] = v;
        }
    }
}

// ------------------------- 6. final layer (4 points per warp) ---------------
__global__ __launch_bounds__(256) void k_final(const __nv_bfloat16* __restrict__ Xhi,
                                               const __nv_bfloat16* __restrict__ Xlo,
                                               const float* __restrict__ wf,
                                               const float* __restrict__ bf,
                                               float* __restrict__ out) {
    __shared__ float swf[KDIM * CLS];
    for (int i = threadIdx.x; i < KDIM * CLS; i += 256) swf[i] = wf[i];
    __syncthreads();
    int warp = (blockIdx.x * 256 + threadIdx.x) >> 5;  // 0..8191
    int lane = threadIdx.x & 31;
#pragma unroll
    for (int pp = 0; pp < 4; pp++) {
        size_t w = (size_t)warp * 4 + pp;
        const __nv_bfloat16* xh = Xhi + w * KP2;
        const __nv_bfloat16* xl = Xlo + w * KP2;
        float acc[CLS];
#pragma unroll
        for (int c = 0; c < CLS; c++) acc[c] = 0.f;
        for (int k = lane; k < KDIM; k += 32) {
            float xv = __bfloat162float(xh[k]) + __bfloat162float(xl[k]);
            const float* wr = &swf[k * CLS];
#pragma unroll
            for (int c = 0; c < CLS; c++) acc[c] += xv * wr[c];
        }
#pragma unroll
        for (int off = 16; off; off >>= 1)
#pragma unroll
            for (int c = 0; c < CLS; c++) acc[c] += __shfl_xor_sync(0xffffffffu, acc[c], off);
        if (lane == 0) {
            float* o = out + w * CLS;
#pragma unroll
            for (int c = 0; c < CLS; c++) o[c] = acc[c] + bf[c];
        }
    }
}

// ------------------------- launch ------------------------------------------
extern "C" void kernel_launch(void* const* d_in, const int* in_sizes, int n_in, void* d_out,
                              int out_size) {
    const float* coarse = (const float*)d_in[1];
    const float* fine0 = (const float*)d_in[2];
    const float* rand_coords = (const float*)d_in[3];
    const float* rand_fill = (const float*)d_in[4];
    const float* w0 = (const float*)d_in[5];
    const float* b0 = (const float*)d_in[6];
    const float* w1 = (const float*)d_in[7];
    const float* b1 = (const float*)d_in[8];
    const float* w2 = (const float*)d_in[9];
    const float* b2 = (const float*)d_in[10];
    const float* wf = (const float*)d_in[11];
    const float* bf = (const float*)d_in[12];
    float* out = (float*)d_out;

    const size_t PROBS = (size_t)Bn * 512 * 512 * CLS;
    const size_t LOGITS = (size_t)Bn * PTR * CLS;
    float* out_probs = out;
    float* out_logits = out + PROBS;
    float* out_coords = out + PROBS + LOGITS;

    void *pXah, *pXal, *pXbh, *pXbl, *pWh, *pWl;
    cudaGetSymbolAddress(&pXah, g_Xa_hi);
    cudaGetSymbolAddress(&pXal, g_Xa_lo);
    cudaGetSymbolAddress(&pXbh, g_Xb_hi);
    cudaGetSymbolAddress(&pXbl, g_Xb_lo);
    cudaGetSymbolAddress(&pWh, g_Wt_hi);
    cudaGetSymbolAddress(&pWl, g_Wt_lo);
    __nv_bfloat16* Xah = (__nv_bfloat16*)pXah;
    __nv_bfloat16* Xal = (__nv_bfloat16*)pXal;
    __nv_bfloat16* Xbh = (__nv_bfloat16*)pXbh;
    __nv_bfloat16* Xbl = (__nv_bfloat16*)pXbl;
    __nv_bfloat16* Wh = (__nv_bfloat16*)pWh;
    __nv_bfloat16* Wl = (__nv_bfloat16*)pWl;

    cudaFuncSetAttribute(k_gemm_mma, cudaFuncAttributeMaxDynamicSharedMemorySize, SM_DYN);

    // fused setup: resize+softmax | prep_w | uncertainty (one launch)
    k_setup<<<5472, 256>>>(coarse, rand_coords, w0, w1, w2, out_probs);

    // per-batch bitonic sort: local sorts + column-merged global stages
    k_lsort<<<32, 1024>>>();
    k_colmerge<<<32, 1024>>>(8192);
    k_lmerge<<<32, 1024>>>(8192);
    k_colmerge<<<32, 1024>>>(16384);
    k_lmerge<<<32, 1024>>>(16384);
    k_colmerge<<<32, 1024>>>(32768);
    k_lmerge_top<<<8, 1024>>>();

    k_sample<<<4096, 256>>>(coarse, fine0, rand_coords, rand_fill, out_coords);

    const int WSTR = 256 * KP2;
    k_gemm_mma<<<512, 256, SM_DYN>>>(Xah, Xal, Wh, Wl, b0, Xbh, Xbl);
    k_gemm_mma<<<512, 256, SM_DYN>>>(Xbh, Xbl, Wh + WSTR, Wl + WSTR, b1, Xah, Xal);
    k_gemm_mma<<<512, 256, SM_DYN>>>(Xah, Xal, Wh + 2 * WSTR, Wl + 2 * WSTR, b2, Xbh, Xbl);
    k_final<<<1024, 256>>>(Xbh, Xbl, wf, bf, out_logits);
}

// round 13
// speedup vs baseline: 1.0318x; 1.0081x over previous
#include <cuda_runtime.h>
#include <cuda_bf16.h>
#include <math.h>
#include <stdint.h>

#define Bn    4
#define COH   128
#define COW   128
#define CLS   19
#define FIH   256
#define FIW   256
#define FIC   256
#define PTR   8192
#define POS   24576
#define NUNC  6144
#define NRAND 2048
#define NSORT 32768
#define KDIM  275
#define NH    256
#define CHUNK 4096
#define KP2   288        // padded K for tensor path (9 x 32)
#define NC    9          // K chunks
#define MTOT  32768      // Bn*PTR

// ------------------------- scratch (device globals, no allocs) -------------
__device__ unsigned long long g_keys[Bn * NSORT];
__device__ __align__(16) __nv_bfloat16 g_Xa_hi[(size_t)MTOT * KP2];
__device__ __align__(16) __nv_bfloat16 g_Xa_lo[(size_t)MTOT * KP2];
__device__ __align__(16) __nv_bfloat16 g_Xb_hi[(size_t)MTOT * KP2];
__device__ __align__(16) __nv_bfloat16 g_Xb_lo[(size_t)MTOT * KP2];
__device__ __align__(16) __nv_bfloat16 g_Wt_hi[3 * 256 * KP2];
__device__ __align__(16) __nv_bfloat16 g_Wt_lo[3 * 256 * KP2];

// ------------------------- small helpers -----------------------------------
__device__ __forceinline__ float lerp_rn(float w, float a, float b) {
    return __fadd_rn(__fmul_rn(__fsub_rn(1.0f, w), a), __fmul_rn(w, b));
}
__device__ __forceinline__ float bf_hi(float v) {
    return __bfloat162float(__float2bfloat16(v));
}
__device__ __forceinline__ uint32_t packbf(float e0, float e1) {
    uint32_t r;
    asm("cvt.rn.bf16x2.f32 %0, %1, %2;" : "=r"(r) : "f"(e1), "f"(e0));
    return r;
}
__device__ __forceinline__ uint32_t smem_u32(const void* p) {
    uint32_t a;
    asm("{ .reg .u64 t; cvta.to.shared.u64 t, %1; cvt.u32.u64 %0, t; }" : "=r"(a) : "l"(p));
    return a;
}
__device__ __forceinline__ void cp16(uint32_t dst, const void* src) {
    asm volatile("cp.async.cg.shared.global [%0], [%1], 16;" :: "r"(dst), "l"(src) : "memory");
}
__device__ __forceinline__ void cp_commit() {
    asm volatile("cp.async.commit_group;" ::: "memory");
}
template <int N>
__device__ __forceinline__ void cp_wait() {
    asm volatile("cp.async.wait_group %0;" :: "n"(N) : "memory");
}
__device__ __forceinline__ void ldsm4(uint32_t r[4], uint32_t addr) {
    asm volatile("ldmatrix.sync.aligned.m8n8.x4.shared.b16 {%0,%1,%2,%3}, [%4];"
                 : "=r"(r[0]), "=r"(r[1]), "=r"(r[2]), "=r"(r[3]) : "r"(addr));
}
__device__ __forceinline__ void ldsm2(uint32_t r[2], uint32_t addr) {
    asm volatile("ldmatrix.sync.aligned.m8n8.x2.shared.b16 {%0,%1}, [%2];"
                 : "=r"(r[0]), "=r"(r[1]) : "r"(addr));
}
__device__ __forceinline__ void mma_bf16(float c[4], const uint32_t a[4], const uint32_t b[2]) {
    asm volatile(
        "mma.sync.aligned.m16n8k16.row.col.f32.bf16.bf16.f32 "
        "{%0,%1,%2,%3}, {%4,%5,%6,%7}, {%8,%9}, {%0,%1,%2,%3};"
        : "+f"(c[0]), "+f"(c[1]), "+f"(c[2]), "+f"(c[3])
        : "r"(a[0]), "r"(a[1]), "r"(a[2]), "r"(a[3]), "r"(b[0]), "r"(b[1]));
}

// fast exp on the FMA/ALU pipes (no MUFU). x <= 0 here; rel err ~1e-7.
__device__ __forceinline__ float fast_exp(float x) {
    float y = x * 1.4426950408889634f;            // log2(e)
    float z = y + 12582912.0f;                    // round-to-nearest-even magic
    int ni = __float_as_int(z) - 0x4B400000;      // integer part n
    float n = z - 12582912.0f;
    float f = y - n;                              // f in [-0.5, 0.5]
    float p = 1.3333558146e-3f;
    p = fmaf(p, f, 9.6181291076e-3f);
    p = fmaf(p, f, 5.5504108664e-2f);
    p = fmaf(p, f, 2.4022650696e-1f);
    p = fmaf(p, f, 6.9314718056e-1f);
    p = fmaf(p, f, 1.0f);                         // 2^f
    return p * __int_as_float((ni + 127) << 23);  // * 2^n
}

// ------------------------- setup bodies (fused into one kernel) -------------
__device__ void body_resize_softmax(int blk, const float* __restrict__ coarse,
                                    float* __restrict__ op) {
    int t = blk * 256 + threadIdx.x;
    int b = t >> 18;
    int rem = t & 262143;
    int y = rem >> 9;
    int x = rem & 511;
    float sy = (y + 0.5f) * 0.25f - 0.5f;
    float sx = (x + 0.5f) * 0.25f - 0.5f;
    float y0f = floorf(sy), x0f = floorf(sx);
    float wy = sy - y0f, wx = sx - x0f;
    int y0 = min(max((int)y0f, 0), COH - 1);
    int y1 = min(max((int)y0f + 1, 0), COH - 1);
    int x0 = min(max((int)x0f, 0), COW - 1);
    int x1 = min(max((int)x0f + 1, 0), COW - 1);
    const float* cb = coarse + (size_t)b * COH * COW * CLS;
    const float* p00 = cb + (y0 * COW + x0) * CLS;
    const float* p01 = cb + (y0 * COW + x1) * CLS;
    const float* p10 = cb + (y1 * COW + x0) * CLS;
    const float* p11 = cb + (y1 * COW + x1) * CLS;
    float v[CLS];
    float m = -3.0e38f;
#pragma unroll
    for (int c = 0; c < CLS; c++) {
        float top = (1.f - wx) * p00[c] + wx * p01[c];
        float bot = (1.f - wx) * p10[c] + wx * p11[c];
        v[c] = (1.f - wy) * top + wy * bot;
        m = fmaxf(m, v[c]);
    }
    float s = 0.f;
#pragma unroll
    for (int c = 0; c < CLS; c++) {
        v[c] = fast_exp(v[c] - m);
        s += v[c];
    }
    float inv = 1.f / s;
    float* o = op + (size_t)t * CLS;
#pragma unroll
    for (int c = 0; c < CLS; c++) o[c] = v[c] * inv;
}

__device__ void body_prep_w(int blk, const float* __restrict__ w0,
                            const float* __restrict__ w1, const float* __restrict__ w2) {
    int t = blk * 256 + threadIdx.x;   // 3*256*288
    if (t >= 3 * 256 * KP2) return;
    int l = t / (256 * KP2);
    int rem = t - l * 256 * KP2;
    int n = rem / KP2, k = rem - n * KP2;
    const float* W = (l == 0) ? w0 : ((l == 1) ? w1 : w2);
    int r;
    if (l == 0) r = (k < 256) ? (k + CLS) : ((k < KDIM) ? (k - 256) : -1);
    else        r = (k < KDIM) ? k : -1;
    float v = (r >= 0) ? W[(size_t)r * NH + n] : 0.f;
    float h = bf_hi(v);
    g_Wt_hi[t] = __float2bfloat16(v);
    g_Wt_lo[t] = __float2bfloat16(v - h);
}

__device__ void body_uncertainty(int blk, const float* __restrict__ coarse,
                                 const float* __restrict__ rc) {
    int t = blk * 256 + threadIdx.x;
    int b = t >> 15;
    int p = t & (NSORT - 1);
    if (p >= POS) { g_keys[t] = ~0ull; return; }
    float cy = rc[((size_t)b * POS + p) * 2 + 0];
    float cx = rc[((size_t)b * POS + p) * 2 + 1];
    float y = __fadd_rn(__fmul_rn(cy, 128.f), -0.5f);
    float x = __fadd_rn(__fmul_rn(cx, 128.f), -0.5f);
    float y0f = floorf(y), x0f = floorf(x);
    float wy = __fsub_rn(y, y0f);
    float wx = __fsub_rn(x, x0f);
    int y0 = min(max((int)y0f, 0), COH - 1);
    int y1 = min(max((int)y0f + 1, 0), COH - 1);
    int x0 = min(max((int)x0f, 0), COW - 1);
    int x1 = min(max((int)x0f + 1, 0), COW - 1);
    const float* cb = coarse + (size_t)b * COH * COW * CLS;
    const float* p00 = cb + (y0 * COW + x0) * CLS;
    const float* p01 = cb + (y0 * COW + x1) * CLS;
    const float* p10 = cb + (y1 * COW + x0) * CLS;
    const float* p11 = cb + (y1 * COW + x1) * CLS;
    float m1 = -3.0e38f, m2 = -3.0e38f;
#pragma unroll
    for (int c = 0; c < CLS; c++) {
        float top = lerp_rn(wx, p00[c], p01[c]);
        float bot = lerp_rn(wx, p10[c], p11[c]);
        float v = lerp_rn(wy, top, bot);
        if (v > m1) { m2 = m1; m1 = v; }
        else if (v > m2) m2 = v;
    }
    float unc = __fsub_rn(m2, m1);
    unsigned u = __float_as_uint(unc);
    u = (u & 0x80000000u) ? ~u : (u | 0x80000000u);
    u = ~u;
    g_keys[t] = ((unsigned long long)u << 32) | (unsigned)p;
}

// one launch: blocks [0,4096) resize | [4096,4960) prep_w | [4960,5472) unc
__global__ __launch_bounds__(256) void k_setup(const float* __restrict__ coarse,
                                               const float* __restrict__ rc,
                                               const float* __restrict__ w0,
                                               const float* __restrict__ w1,
                                               const float* __restrict__ w2,
                                               float* __restrict__ out_probs) {
    int blk = blockIdx.x;
    if (blk < 4096) body_resize_softmax(blk, coarse, out_probs);
    else if (blk < 4960) body_prep_w(blk - 4096, w0, w1, w2);
    else body_uncertainty(blk - 4960, coarse, rc);
}

// ------------------------- 2. bitonic sort ---------------------------------
__global__ __launch_bounds__(1024) void k_lsort() {
    __shared__ unsigned long long s[CHUNK];
    int base = blockIdx.x * CHUNK;
    int lbase = base & (NSORT - 1);
    for (int i = threadIdx.x; i < CHUNK; i += 1024) s[i] = g_keys[base + i];
    __syncthreads();
    for (int k = 2; k <= CHUNK; k <<= 1) {
        for (int j = k >> 1; j >= 64; j >>= 1) {
#pragma unroll
            for (int r = 0; r < 2; r++) {
                int t = threadIdx.x + r * 1024;
                int i = ((t & ~(j - 1)) << 1) | (t & (j - 1));
                int ixj = i + j;
                bool up = (((lbase + i) & k) == 0);
                unsigned long long A = s[i], Bv = s[ixj];
                if ((A > Bv) == up) { s[i] = Bv; s[ixj] = A; }
            }
            __syncthreads();
        }
        int j0 = (k >> 1) < 32 ? (k >> 1) : 32;
        for (int j = j0; j > 0; j >>= 1) {
#pragma unroll
            for (int r = 0; r < 2; r++) {
                int t = threadIdx.x + r * 1024;
                int i = ((t & ~(j - 1)) << 1) | (t & (j - 1));
                int ixj = i + j;
                bool up = (((lbase + i) & k) == 0);
                unsigned long long A = s[i], Bv = s[ixj];
                if ((A > Bv) == up) { s[i] = Bv; s[ixj] = A; }
            }
            __syncwarp();
        }
        __syncthreads();
    }
    for (int i = threadIdx.x; i < CHUNK; i += 1024) g_keys[base + i] = s[i];
}

// column merge: all global passes (j >= 4096) of stage k in one smem residency.
__global__ __launch_bounds__(1024) void k_colmerge(int k) {
    __shared__ unsigned long long s[CHUNK];
    int b = blockIdx.x >> 3, st = blockIdx.x & 7;
    size_t base = (size_t)b * NSORT + st * 512;
    for (int e = threadIdx.x; e < CHUNK; e += 1024)
        s[e] = g_keys[base + (size_t)(e >> 9) * 4096 + (e & 511)];
    __syncthreads();
    for (int j = k >> 1; j >= 4096; j >>= 1) {
        int jl = j >> 3;
#pragma unroll
        for (int r = 0; r < 2; r++) {
            int t = threadIdx.x + r * 1024;
            int i = ((t & ~(jl - 1)) << 1) | (t & (jl - 1));
            int ixj = i + jl;
            bool up = ((((i >> 9) * 4096) & k) == 0);
            unsigned long long A = s[i], Bv = s[ixj];
            if ((A > Bv) == up) { s[i] = Bv; s[ixj] = A; }
        }
        __syncthreads();
    }
    for (int e = threadIdx.x; e < CHUNK; e += 1024)
        g_keys[base + (size_t)(e >> 9) * 4096 + (e & 511)] = s[e];
}

__device__ __forceinline__ void lmerge_body(int base, int lbase, int k) {
    __shared__ unsigned long long s[CHUNK];
    for (int i = threadIdx.x; i < CHUNK; i += 1024) s[i] = g_keys[base + i];
    __syncthreads();
    for (int j = CHUNK >> 1; j >= 64; j >>= 1) {
#pragma unroll
        for (int r = 0; r < 2; r++) {
            int t = threadIdx.x + r * 1024;
            int i = ((t & ~(j - 1)) << 1) | (t & (j - 1));
            int ixj = i + j;
            bool up = (((lbase + i) & k) == 0);
            unsigned long long A = s[i], Bv = s[ixj];
            if ((A > Bv) == up) { s[i] = Bv; s[ixj] = A; }
        }
        __syncthreads();
    }
    for (int j = 32; j > 0; j >>= 1) {
#pragma unroll
        for (int r = 0; r < 2; r++) {
            int t = threadIdx.x + r * 1024;
            int i = ((t & ~(j - 1)) << 1) | (t & (j - 1));
            int ixj = i + j;
            bool up = (((lbase + i) & k) == 0);
            unsigned long long A = s[i], Bv = s[ixj];
            if ((A > Bv) == up) { s[i] = Bv; s[ixj] = A; }
        }
        __syncwarp();
    }
    __syncthreads();
    for (int i = threadIdx.x; i < CHUNK; i += 1024) g_keys[base + i] = s[i];
}

__global__ __launch_bounds__(1024) void k_lmerge(int k) {
    int base = blockIdx.x * CHUNK;
    lmerge_body(base, base & (NSORT - 1), k);
}

__global__ __launch_bounds__(1024) void k_lmerge_top() {
    int b = blockIdx.x >> 1, c = blockIdx.x & 1;
    lmerge_body(b * NSORT + c * CHUNK, c * CHUNK, NSORT);
}

// ------------------------- 4. sampling + coords -> bf16 hi/lo ---------------
__global__ void k_sample(const float* __restrict__ coarse, const float* __restrict__ fine,
                         const float* __restrict__ rc, const float* __restrict__ rf,
                         float* __restrict__ oc) {
    int gt = blockIdx.x * 256 + threadIdx.x;
    int w = gt >> 5, lane = gt & 31;
    int b = w >> 13, p = w & (PTR - 1);
    float cy, cx;
    if (p < NUNC) {
        unsigned idx = (unsigned)(g_keys[(size_t)b * NSORT + p] & 0xffffffffu);
        cy = rc[((size_t)b * POS + idx) * 2 + 0];
        cx = rc[((size_t)b * POS + idx) * 2 + 1];
    } else {
        int q = p - NUNC;
        cy = rf[((size_t)b * NRAND + q) * 2 + 0];
        cx = rf[((size_t)b * NRAND + q) * 2 + 1];
    }
    if (lane == 0) {
        oc[(size_t)w * 2 + 0] = cy;
        oc[(size_t)w * 2 + 1] = cx;
    }
    size_t row = (size_t)w * KP2;

    {   // fine -> cols [0..255] of Xa
        float y = cy * 256.f - 0.5f, x = cx * 256.f - 0.5f;
        float y0f = floorf(y), x0f = floorf(x);
        float wy = y - y0f, wx = x - x0f;
        int y0 = min(max((int)y0f, 0), FIH - 1);
        int y1 = min(max((int)y0f + 1, 0), FIH - 1);
        int x0 = min(max((int)x0f, 0), FIW - 1);
        int x1 = min(max((int)x0f + 1, 0), FIW - 1);
        const float* fb = fine + (size_t)b * FIH * FIW * FIC;
        const float4* f00 = (const float4*)(fb + ((size_t)y0 * FIW + x0) * FIC);
        const float4* f01 = (const float4*)(fb + ((size_t)y0 * FIW + x1) * FIC);
        const float4* f10 = (const float4*)(fb + ((size_t)y1 * FIW + x0) * FIC);
        const float4* f11 = (const float4*)(fb + ((size_t)y1 * FIW + x1) * FIC);
#pragma unroll
        for (int q = 0; q < 2; q++) {
            int c4 = lane + 32 * q;
            float4 a = f00[c4], b2 = f01[c4], c = f10[c4], d = f11[c4];
            float r0 = (1.f - wy) * ((1.f - wx) * a.x + wx * b2.x) + wy * ((1.f - wx) * c.x + wx * d.x);
            float r1 = (1.f - wy) * ((1.f - wx) * a.y + wx * b2.y) + wy * ((1.f - wx) * c.y + wx * d.y);
            float r2 = (1.f - wy) * ((1.f - wx) * a.z + wx * b2.z) + wy * ((1.f - wx) * c.z + wx * d.z);
            float r3 = (1.f - wy) * ((1.f - wx) * a.w + wx * b2.w) + wy * ((1.f - wx) * c.w + wx * d.w);
            uint2 hv, lv;
            hv.x = packbf(r0, r1); hv.y = packbf(r2, r3);
            lv.x = packbf(r0 - bf_hi(r0), r1 - bf_hi(r1));
            lv.y = packbf(r2 - bf_hi(r2), r3 - bf_hi(r3));
            *(uint2*)&g_Xa_hi[row + (size_t)c4 * 4] = hv;
            *(uint2*)&g_Xa_lo[row + (size_t)c4 * 4] = lv;
        }
    }
    {   // coarse residual -> cols [256..287] of Xa AND Xb (zeros past 274)
        float y = cy * 128.f - 0.5f, x = cx * 128.f - 0.5f;
        float y0f = floorf(y), x0f = floorf(x);
        float wy = y - y0f, wx = x - x0f;
        int y0 = min(max((int)y0f, 0), COH - 1);
        int y1 = min(max((int)y0f + 1, 0), COH - 1);
        int x0 = min(max((int)x0f, 0), COW - 1);
        int x1 = min(max((int)x0f + 1, 0), COW - 1);
        const float* cb = coarse + (size_t)b * COH * COW * CLS;
        int c = lane;
        float v = 0.f;
        if (c < CLS) {
            float a = cb[(y0 * COW + x0) * CLS + c];
            float b2 = cb[(y0 * COW + x1) * CLS + c];
            float cc = cb[(y1 * COW + x0) * CLS + c];
            float d = cb[(y1 * COW + x1) * CLS + c];
            v = (1.f - wy) * ((1.f - wx) * a + wx * b2) + wy * ((1.f - wx) * cc + wx * d);
        }
        __nv_bfloat16 hv = __float2bfloat16(v);
        __nv_bfloat16 lv = __float2bfloat16(v - bf_hi(v));
        size_t off = row + 256 + lane;
        g_Xa_hi[off] = hv; g_Xa_lo[off] = lv;
        g_Xb_hi[off] = hv; g_Xb_lo[off] = lv;
    }
}

// ------------------------- 5. HMMA GEMM (bf16 hi/lo split, R5 config) ------
#define PADK 40                      // smem row stride in bf16 (80 B)
#define ABYTES (128 * PADK * 2)      // 10240
#define BUFB   (4 * ABYTES)          // hi/lo x A/B per stage = 40960
#define SM_DYN (3 * BUFB)            // 122880 (3-stage pipeline)
#define RSTR   272                   // epilogue staging row stride (bytes)

__global__ __launch_bounds__(256) void k_gemm_mma(
    const __nv_bfloat16* __restrict__ Xhi, const __nv_bfloat16* __restrict__ Xlo,
    const __nv_bfloat16* __restrict__ Whi, const __nv_bfloat16* __restrict__ Wlo,
    const float* __restrict__ bias,
    __nv_bfloat16* __restrict__ Yhi, __nv_bfloat16* __restrict__ Ylo) {
    extern __shared__ char smem[];
    __shared__ float sbias[128];
    uint32_t sb = smem_u32(smem);
    int tid = threadIdx.x, wid = tid >> 5, lane = tid & 31;
    int wm = wid & 1, wn = wid >> 1;           // warp grid 2 (M) x 4 (N)
    int m0 = (blockIdx.x >> 1) * 128;
    int n0 = (blockIdx.x & 1) * 128;

    if (tid < 128) sbias[tid] = bias[n0 + tid];

    float acc[4][4][4];
#pragma unroll
    for (int i = 0; i < 4; i++)
#pragma unroll
        for (int j = 0; j < 4; j++)
#pragma unroll
            for (int q = 0; q < 4; q++) acc[i][j][q] = 0.f;

    int lrow = tid >> 2;
    int lq = tid & 3;

    auto issue = [&](int c, int buf) {
        int kb = c * 32;
        uint32_t s0 = sb + buf * BUFB;
#pragma unroll
        for (int r = 0; r < 2; r++) {
            int row = lrow + r * 64;
            size_t gA = (size_t)(m0 + row) * KP2 + kb + lq * 8;
            size_t gB = (size_t)(n0 + row) * KP2 + kb + lq * 8;
            uint32_t soff = row * (PADK * 2) + lq * 16;
            cp16(s0 + soff, Xhi + gA);
            cp16(s0 + ABYTES + soff, Xlo + gA);
            cp16(s0 + 2 * ABYTES + soff, Whi + gB);
            cp16(s0 + 3 * ABYTES + soff, Wlo + gB);
        }
        cp_commit();
    };

    issue(0, 0);
    issue(1, 1);

    for (int c = 0; c < NC; c++) {
        if (c <= NC - 3) { issue(c + 2, (c + 2) % 3); cp_wait<2>(); }
        else if (c == NC - 2) cp_wait<1>();
        else cp_wait<0>();
        __syncthreads();
        uint32_t s0 = sb + (c % 3) * BUFB;
#pragma unroll
        for (int k16 = 0; k16 < 2; k16++) {
            uint32_t ah[4][4], al[4][4], bh[4][2], bl[4][2];
            int ka = k16 * 32 + ((lane >> 4) << 4);
            int kb2 = k16 * 32 + (((lane >> 3) & 1) << 4);
#pragma unroll
            for (int mt = 0; mt < 4; mt++) {
                int row = wm * 64 + mt * 16 + (lane & 15);
                uint32_t a = s0 + row * (PADK * 2) + ka;
                ldsm4(ah[mt], a);
                ldsm4(al[mt], a + ABYTES);
            }
#pragma unroll
            for (int nt = 0; nt < 4; nt++) {
                int n = wn * 32 + nt * 8 + (lane & 7);
                uint32_t a = s0 + 2 * ABYTES + n * (PADK * 2) + kb2;
                ldsm2(bh[nt], a);
                ldsm2(bl[nt], a + ABYTES);
            }
#pragma unroll
            for (int mt = 0; mt < 4; mt++)
#pragma unroll
                for (int nt = 0; nt < 4; nt++) {
                    mma_bf16(acc[mt][nt], ah[mt], bh[nt]);
                    mma_bf16(acc[mt][nt], ah[mt], bl[nt]);
                    mma_bf16(acc[mt][nt], al[mt], bh[nt]);
                }
        }
        __syncthreads();
    }

    // epilogue: bias + relu, stage in smem, coalesced uint4 stores (hi then lo)
#pragma unroll
    for (int pass = 0; pass < 2; pass++) {
        __syncthreads();
#pragma unroll
        for (int mt = 0; mt < 4; mt++)
#pragma unroll
            for (int nt = 0; nt < 4; nt++) {
                int col = wn * 32 + nt * 8 + (lane & 3) * 2;
                float bi0 = sbias[col], bi1 = sbias[col + 1];
#pragma unroll
                for (int h = 0; h < 2; h++) {
                    int row = wm * 64 + mt * 16 + (lane >> 2) + h * 8;
                    float v0 = acc[mt][nt][2 * h] + bi0;
                    float v1 = acc[mt][nt][2 * h + 1] + bi1;
                    v0 = v0 > 0.f ? v0 : 0.f;
                    v1 = v1 > 0.f ? v1 : 0.f;
                    uint32_t pv = (pass == 0)
                        ? packbf(v0, v1)
                        : packbf(v0 - bf_hi(v0), v1 - bf_hi(v1));
                    *(uint32_t*)(smem + row * RSTR + col * 2) = pv;
                }
            }
        __syncthreads();
        __nv_bfloat16* Y = (pass == 0) ? Yhi : Ylo;
#pragma unroll
        for (int i = 0; i < 8; i++) {
            int u = tid + i * 256;
            int row = u >> 4, q = u & 15;
            uint4 v = *(uint4*)(smem + row * RSTR + q * 16);
            *(uint4*)&Y[(size_t)(m0 + row) * KP2 + n0 + q * 8] = v;
        }
    }
}

// ------------------------- 6. final layer (N=19) ---------------------------
__global__ __launch_bounds__(256) void k_final(const __nv_bfloat16* __restrict__ Xhi,
                                               const __nv_bfloat16* __restrict__ Xlo,
                                               const float* __restrict__ wf,
                                               const float* __restrict__ bf,
                                               float* __restrict__ out) {
    __shared__ float swf[KDIM * CLS];
    for (int i = threadIdx.x; i < KDIM * CLS; i += 256) swf[i] = wf[i];
    __syncthreads();
    int w = (blockIdx.x * 256 + threadIdx.x) >> 5;
    int lane = threadIdx.x & 31;
    const __nv_bfloat16* xh = Xhi + (size_t)w * KP2;
    const __nv_bfloat16* xl = Xlo + (size_t)w * KP2;
    float acc[CLS];
#pragma unroll
    for (int c = 0; c < CLS; c++) acc[c] = 0.f;
    for (int k = lane; k < KDIM; k += 32) {
        float xv = __bfloat162float(xh[k]) + __bfloat162float(xl[k]);
        const float* wr = &swf[k * CLS];
#pragma unroll
        for (int c = 0; c < CLS; c++) acc[c] += xv * wr[c];
    }
#pragma unroll
    for (int off = 16; off; off >>= 1)
#pragma unroll
        for (int c = 0; c < CLS; c++) acc[c] += __shfl_xor_sync(0xffffffffu, acc[c], off);
    if (lane == 0) {
        float* o = out + (size_t)w * CLS;
#pragma unroll
        for (int c = 0; c < CLS; c++) o[c] = acc[c] + bf[c];
    }
}

// ------------------------- launch ------------------------------------------
extern "C" void kernel_launch(void* const* d_in, const int* in_sizes, int n_in, void* d_out,
                              int out_size) {
    const float* coarse = (const float*)d_in[1];
    const float* fine0 = (const float*)d_in[2];
    const float* rand_coords = (const float*)d_in[3];
    const float* rand_fill = (const float*)d_in[4];
    const float* w0 = (const float*)d_in[5];
    const float* b0 = (const float*)d_in[6];
    const float* w1 = (const float*)d_in[7];
    const float* b1 = (const float*)d_in[8];
    const float* w2 = (const float*)d_in[9];
    const float* b2 = (const float*)d_in[10];
    const float* wf = (const float*)d_in[11];
    const float* bf = (const float*)d_in[12];
    float* out = (float*)d_out;

    const size_t PROBS = (size_t)Bn * 512 * 512 * CLS;
    const size_t LOGITS = (size_t)Bn * PTR * CLS;
    float* out_probs = out;
    float* out_logits = out + PROBS;
    float* out_coords = out + PROBS + LOGITS;

    void *pXah, *pXal, *pXbh, *pXbl, *pWh, *pWl;
    cudaGetSymbolAddress(&pXah, g_Xa_hi);
    cudaGetSymbolAddress(&pXal, g_Xa_lo);
    cudaGetSymbolAddress(&pXbh, g_Xb_hi);
    cudaGetSymbolAddress(&pXbl, g_Xb_lo);
    cudaGetSymbolAddress(&pWh, g_Wt_hi);
    cudaGetSymbolAddress(&pWl, g_Wt_lo);
    __nv_bfloat16* Xah = (__nv_bfloat16*)pXah;
    __nv_bfloat16* Xal = (__nv_bfloat16*)pXal;
    __nv_bfloat16* Xbh = (__nv_bfloat16*)pXbh;
    __nv_bfloat16* Xbl = (__nv_bfloat16*)pXbl;
    __nv_bfloat16* Wh = (__nv_bfloat16*)pWh;
    __nv_bfloat16* Wl = (__nv_bfloat16*)pWl;

    cudaFuncSetAttribute(k_gemm_mma, cudaFuncAttributeMaxDynamicSharedMemorySize, SM_DYN);

    // fused setup: resize+softmax (fast exp) | prep_w | uncertainty
    k_setup<<<5472, 256>>>(coarse, rand_coords, w0, w1, w2, out_probs);

    // per-batch bitonic sort: local sorts + column-merged global stages
    k_lsort<<<32, 1024>>>();
    k_colmerge<<<32, 1024>>>(8192);
    k_lmerge<<<32, 1024>>>(8192);
    k_colmerge<<<32, 1024>>>(16384);
    k_lmerge<<<32, 1024>>>(16384);
    k_colmerge<<<32, 1024>>>(32768);
    k_lmerge_top<<<8, 1024>>>();

    k_sample<<<4096, 256>>>(coarse, fine0, rand_coords, rand_fill, out_coords);

    const int WSTR = 256 * KP2;
    k_gemm_mma<<<512, 256, SM_DYN>>>(Xah, Xal, Wh, Wl, b0, Xbh, Xbl);
    k_gemm_mma<<<512, 256, SM_DYN>>>(Xbh, Xbl, Wh + WSTR, Wl + WSTR, b1, Xah, Xal);
    k_gemm_mma<<<512, 256, SM_DYN>>>(Xah, Xal, Wh + 2 * WSTR, Wl + 2 * WSTR, b2, Xbh, Xbl);
    k_final<<<4096, 256>>>(Xbh, Xbl, wf, bf, out_logits);
}

// round 15
// speedup vs baseline: 1.0950x; 1.0612x over previous
#include <cuda_runtime.h>
#include <cuda_bf16.h>
#include <math.h>
#include <stdint.h>

#define Bn    4
#define COH   128
#define COW   128
#define CLS   19
#define FIH   256
#define FIW   256
#define FIC   256
#define PTR   8192
#define POS   24576
#define NUNC  6144
#define NRAND 2048
#define NSORT 32768
#define KDIM  275
#define NH    256
#define CHUNK 4096
#define KP2   288        // padded K for tensor path (9 x 32)
#define NC    9          // K chunks
#define MTOT  32768      // Bn*PTR

// ------------------------- scratch (device globals, no allocs) -------------
__device__ unsigned long long g_keys[Bn * NSORT];
__device__ __align__(16) __nv_bfloat16 g_Xa_hi[(size_t)MTOT * KP2];
__device__ __align__(16) __nv_bfloat16 g_Xa_lo[(size_t)MTOT * KP2];
__device__ __align__(16) __nv_bfloat16 g_Xb_hi[(size_t)MTOT * KP2];
__device__ __align__(16) __nv_bfloat16 g_Xb_lo[(size_t)MTOT * KP2];
__device__ __align__(16) __nv_bfloat16 g_Wt_hi[3 * 256 * KP2];
__device__ __align__(16) __nv_bfloat16 g_Wt_lo[3 * 256 * KP2];

// ------------------------- small helpers -----------------------------------
__device__ __forceinline__ float lerp_rn(float w, float a, float b) {
    return __fadd_rn(__fmul_rn(__fsub_rn(1.0f, w), a), __fmul_rn(w, b));
}
__device__ __forceinline__ float bf_hi(float v) {
    return __bfloat162float(__float2bfloat16(v));
}
__device__ __forceinline__ uint32_t packbf(float e0, float e1) {
    uint32_t r;
    asm("cvt.rn.bf16x2.f32 %0, %1, %2;" : "=r"(r) : "f"(e1), "f"(e0));
    return r;
}
__device__ __forceinline__ uint32_t smem_u32(const void* p) {
    uint32_t a;
    asm("{ .reg .u64 t; cvta.to.shared.u64 t, %1; cvt.u32.u64 %0, t; }" : "=r"(a) : "l"(p));
    return a;
}
__device__ __forceinline__ void cp16(uint32_t dst, const void* src) {
    asm volatile("cp.async.cg.shared.global [%0], [%1], 16;" :: "r"(dst), "l"(src) : "memory");
}
__device__ __forceinline__ void cp_commit() {
    asm volatile("cp.async.commit_group;" ::: "memory");
}
template <int N>
__device__ __forceinline__ void cp_wait() {
    asm volatile("cp.async.wait_group %0;" :: "n"(N) : "memory");
}
__device__ __forceinline__ void ldsm4(uint32_t r[4], uint32_t addr) {
    asm volatile("ldmatrix.sync.aligned.m8n8.x4.shared.b16 {%0,%1,%2,%3}, [%4];"
                 : "=r"(r[0]), "=r"(r[1]), "=r"(r[2]), "=r"(r[3]) : "r"(addr));
}
__device__ __forceinline__ void ldsm2(uint32_t r[2], uint32_t addr) {
    asm volatile("ldmatrix.sync.aligned.m8n8.x2.shared.b16 {%0,%1}, [%2];"
                 : "=r"(r[0]), "=r"(r[1]) : "r"(addr));
}
__device__ __forceinline__ void mma_bf16(float c[4], const uint32_t a[4], const uint32_t b[2]) {
    asm volatile(
        "mma.sync.aligned.m16n8k16.row.col.f32.bf16.bf16.f32 "
        "{%0,%1,%2,%3}, {%4,%5,%6,%7}, {%8,%9}, {%0,%1,%2,%3};"
        : "+f"(c[0]), "+f"(c[1]), "+f"(c[2]), "+f"(c[3])
        : "r"(a[0]), "r"(a[1]), "r"(a[2]), "r"(a[3]), "r"(b[0]), "r"(b[1]));
}

// ------------------------- setup bodies (fused into one kernel) -------------
__device__ void body_resize_softmax(int blk, const float* __restrict__ coarse,
                                    float* __restrict__ op) {
    int t = blk * 256 + threadIdx.x;
    int b = t >> 18;
    int rem = t & 262143;
    int y = rem >> 9;
    int x = rem & 511;
    float sy = (y + 0.5f) * 0.25f - 0.5f;
    float sx = (x + 0.5f) * 0.25f - 0.5f;
    float y0f = floorf(sy), x0f = floorf(sx);
    float wy = sy - y0f, wx = sx - x0f;
    int y0 = min(max((int)y0f, 0), COH - 1);
    int y1 = min(max((int)y0f + 1, 0), COH - 1);
    int x0 = min(max((int)x0f, 0), COW - 1);
    int x1 = min(max((int)x0f + 1, 0), COW - 1);
    const float* cb = coarse + (size_t)b * COH * COW * CLS;
    const float* p00 = cb + (y0 * COW + x0) * CLS;
    const float* p01 = cb + (y0 * COW + x1) * CLS;
    const float* p10 = cb + (y1 * COW + x0) * CLS;
    const float* p11 = cb + (y1 * COW + x1) * CLS;
    float v[CLS];
    float m = -3.0e38f;
#pragma unroll
    for (int c = 0; c < CLS; c++) {
        float top = (1.f - wx) * p00[c] + wx * p01[c];
        float bot = (1.f - wx) * p10[c] + wx * p11[c];
        v[c] = (1.f - wy) * top + wy * bot;
        m = fmaxf(m, v[c]);
    }
    float s = 0.f;
#pragma unroll
    for (int c = 0; c < CLS; c++) {
        v[c] = expf(v[c] - m);
        s += v[c];
    }
    float inv = 1.f / s;
    float* o = op + (size_t)t * CLS;
#pragma unroll
    for (int c = 0; c < CLS; c++) o[c] = v[c] * inv;
}

__device__ void body_prep_w(int blk, const float* __restrict__ w0,
                            const float* __restrict__ w1, const float* __restrict__ w2) {
    int t = blk * 256 + threadIdx.x;   // 3*256*288
    if (t >= 3 * 256 * KP2) return;
    int l = t / (256 * KP2);
    int rem = t - l * 256 * KP2;
    int n = rem / KP2, k = rem - n * KP2;
    const float* W = (l == 0) ? w0 : ((l == 1) ? w1 : w2);
    int r;
    if (l == 0) r = (k < 256) ? (k + CLS) : ((k < KDIM) ? (k - 256) : -1);
    else        r = (k < KDIM) ? k : -1;
    float v = (r >= 0) ? W[(size_t)r * NH + n] : 0.f;
    float h = bf_hi(v);
    g_Wt_hi[t] = __float2bfloat16(v);
    g_Wt_lo[t] = __float2bfloat16(v - h);
}

__device__ void body_uncertainty(int blk, const float* __restrict__ coarse,
                                 const float* __restrict__ rc) {
    int t = blk * 256 + threadIdx.x;
    int b = t >> 15;
    int p = t & (NSORT - 1);
    if (p >= POS) { g_keys[t] = ~0ull; return; }
    float cy = rc[((size_t)b * POS + p) * 2 + 0];
    float cx = rc[((size_t)b * POS + p) * 2 + 1];
    float y = __fadd_rn(__fmul_rn(cy, 128.f), -0.5f);
    float x = __fadd_rn(__fmul_rn(cx, 128.f), -0.5f);
    float y0f = floorf(y), x0f = floorf(x);
    float wy = __fsub_rn(y, y0f);
    float wx = __fsub_rn(x, x0f);
    int y0 = min(max((int)y0f, 0), COH - 1);
    int y1 = min(max((int)y0f + 1, 0), COH - 1);
    int x0 = min(max((int)x0f, 0), COW - 1);
    int x1 = min(max((int)x0f + 1, 0), COW - 1);
    const float* cb = coarse + (size_t)b * COH * COW * CLS;
    const float* p00 = cb + (y0 * COW + x0) * CLS;
    const float* p01 = cb + (y0 * COW + x1) * CLS;
    const float* p10 = cb + (y1 * COW + x0) * CLS;
    const float* p11 = cb + (y1 * COW + x1) * CLS;
    float m1 = -3.0e38f, m2 = -3.0e38f;
#pragma unroll
    for (int c = 0; c < CLS; c++) {
        float top = lerp_rn(wx, p00[c], p01[c]);
        float bot = lerp_rn(wx, p10[c], p11[c]);
        float v = lerp_rn(wy, top, bot);
        if (v > m1) { m2 = m1; m1 = v; }
        else if (v > m2) m2 = v;
    }
    float unc = __fsub_rn(m2, m1);
    unsigned u = __float_as_uint(unc);
    u = (u & 0x80000000u) ? ~u : (u | 0x80000000u);
    u = ~u;
    g_keys[t] = ((unsigned long long)u << 32) | (unsigned)p;
}

// one launch: blocks [0,4096) resize | [4096,4960) prep_w | [4960,5472) unc
__global__ __launch_bounds__(256) void k_setup(const float* __restrict__ coarse,
                                               const float* __restrict__ rc,
                                               const float* __restrict__ w0,
                                               const float* __restrict__ w1,
                                               const float* __restrict__ w2,
                                               float* __restrict__ out_probs) {
    int blk = blockIdx.x;
    if (blk < 4096) body_resize_softmax(blk, coarse, out_probs);
    else if (blk < 4960) body_prep_w(blk - 4096, w0, w1, w2);
    else body_uncertainty(blk - 4960, coarse, rc);
}

// ------------------------- 2. bitonic sort ---------------------------------
__global__ __launch_bounds__(1024) void k_lsort() {
    __shared__ unsigned long long s[CHUNK];
    int base = blockIdx.x * CHUNK;
    int lbase = base & (NSORT - 1);
    for (int i = threadIdx.x; i < CHUNK; i += 1024) s[i] = g_keys[base + i];
    __syncthreads();
    for (int k = 2; k <= CHUNK; k <<= 1) {
        for (int j = k >> 1; j >= 64; j >>= 1) {
#pragma unroll
            for (int r = 0; r < 2; r++) {
                int t = threadIdx.x + r * 1024;
                int i = ((t & ~(j - 1)) << 1) | (t & (j - 1));
                int ixj = i + j;
                bool up = (((lbase + i) & k) == 0);
                unsigned long long A = s[i], Bv = s[ixj];
                if ((A > Bv) == up) { s[i] = Bv; s[ixj] = A; }
            }
            __syncthreads();
        }
        int j0 = (k >> 1) < 32 ? (k >> 1) : 32;
        for (int j = j0; j > 0; j >>= 1) {
#pragma unroll
            for (int r = 0; r < 2; r++) {
                int t = threadIdx.x + r * 1024;
                int i = ((t & ~(j - 1)) << 1) | (t & (j - 1));
                int ixj = i + j;
                bool up = (((lbase + i) & k) == 0);
                unsigned long long A = s[i], Bv = s[ixj];
                if ((A > Bv) == up) { s[i] = Bv; s[ixj] = A; }
            }
            __syncwarp();
        }
        __syncthreads();
    }
    for (int i = threadIdx.x; i < CHUNK; i += 1024) g_keys[base + i] = s[i];
}

// column merge: all global passes (j >= 4096) of stage k in one smem residency.
__global__ __launch_bounds__(1024) void k_colmerge(int k) {
    __shared__ unsigned long long s[CHUNK];
    int b = blockIdx.x >> 3, st = blockIdx.x & 7;
    size_t base = (size_t)b * NSORT + st * 512;
    for (int e = threadIdx.x; e < CHUNK; e += 1024)
        s[e] = g_keys[base + (size_t)(e >> 9) * 4096 + (e & 511)];
    __syncthreads();
    for (int j = k >> 1; j >= 4096; j >>= 1) {
        int jl = j >> 3;
#pragma unroll
        for (int r = 0; r < 2; r++) {
            int t = threadIdx.x + r * 1024;
            int i = ((t & ~(jl - 1)) << 1) | (t & (jl - 1));
            int ixj = i + jl;
            bool up = ((((i >> 9) * 4096) & k) == 0);
            unsigned long long A = s[i], Bv = s[ixj];
            if ((A > Bv) == up) { s[i] = Bv; s[ixj] = A; }
        }
        __syncthreads();
    }
    for (int e = threadIdx.x; e < CHUNK; e += 1024)
        g_keys[base + (size_t)(e >> 9) * 4096 + (e & 511)] = s[e];
}

__device__ __forceinline__ void lmerge_body(int base, int lbase, int k) {
    __shared__ unsigned long long s[CHUNK];
    for (int i = threadIdx.x; i < CHUNK; i += 1024) s[i] = g_keys[base + i];
    __syncthreads();
    for (int j = CHUNK >> 1; j >= 64; j >>= 1) {
#pragma unroll
        for (int r = 0; r < 2; r++) {
            int t = threadIdx.x + r * 1024;
            int i = ((t & ~(j - 1)) << 1) | (t & (j - 1));
            int ixj = i + j;
            bool up = (((lbase + i) & k) == 0);
            unsigned long long A = s[i], Bv = s[ixj];
            if ((A > Bv) == up) { s[i] = Bv; s[ixj] = A; }
        }
        __syncthreads();
    }
    for (int j = 32; j > 0; j >>= 1) {
#pragma unroll
        for (int r = 0; r < 2; r++) {
            int t = threadIdx.x + r * 1024;
            int i = ((t & ~(j - 1)) << 1) | (t & (j - 1));
            int ixj = i + j;
            bool up = (((lbase + i) & k) == 0);
            unsigned long long A = s[i], Bv = s[ixj];
            if ((A > Bv) == up) { s[i] = Bv; s[ixj] = A; }
        }
        __syncwarp();
    }
    __syncthreads();
    for (int i = threadIdx.x; i < CHUNK; i += 1024) g_keys[base + i] = s[i];
}

__global__ __launch_bounds__(1024) void k_lmerge(int k) {
    int base = blockIdx.x * CHUNK;
    lmerge_body(base, base & (NSORT - 1), k);
}

__global__ __launch_bounds__(1024) void k_lmerge_top() {
    int b = blockIdx.x >> 1, c = blockIdx.x & 1;
    lmerge_body(b * NSORT + c * CHUNK, c * CHUNK, NSORT);
}

// ------------------------- 4. sampling + coords -> bf16 hi/lo ---------------
__global__ void k_sample(const float* __restrict__ coarse, const float* __restrict__ fine,
                         const float* __restrict__ rc, const float* __restrict__ rf,
                         float* __restrict__ oc) {
    int gt = blockIdx.x * 256 + threadIdx.x;
    int w = gt >> 5, lane = gt & 31;
    int b = w >> 13, p = w & (PTR - 1);
    float cy, cx;
    if (p < NUNC) {
        unsigned idx = (unsigned)(g_keys[(size_t)b * NSORT + p] & 0xffffffffu);
        cy = rc[((size_t)b * POS + idx) * 2 + 0];
        cx = rc[((size_t)b * POS + idx) * 2 + 1];
    } else {
        int q = p - NUNC;
        cy = rf[((size_t)b * NRAND + q) * 2 + 0];
        cx = rf[((size_t)b * NRAND + q) * 2 + 1];
    }
    if (lane == 0) {
        oc[(size_t)w * 2 + 0] = cy;
        oc[(size_t)w * 2 + 1] = cx;
    }
    size_t row = (size_t)w * KP2;

    {   // fine -> cols [0..255] of Xa
        float y = cy * 256.f - 0.5f, x = cx * 256.f - 0.5f;
        float y0f = floorf(y), x0f = floorf(x);
        float wy = y - y0f, wx = x - x0f;
        int y0 = min(max((int)y0f, 0), FIH - 1);
        int y1 = min(max((int)y0f + 1, 0), FIH - 1);
        int x0 = min(max((int)x0f, 0), FIW - 1);
        int x1 = min(max((int)x0f + 1, 0), FIW - 1);
        const float* fb = fine + (size_t)b * FIH * FIW * FIC;
        const float4* f00 = (const float4*)(fb + ((size_t)y0 * FIW + x0) * FIC);
        const float4* f01 = (const float4*)(fb + ((size_t)y0 * FIW + x1) * FIC);
        const float4* f10 = (const float4*)(fb + ((size_t)y1 * FIW + x0) * FIC);
        const float4* f11 = (const float4*)(fb + ((size_t)y1 * FIW + x1) * FIC);
#pragma unroll
        for (int q = 0; q < 2; q++) {
            int c4 = lane + 32 * q;
            float4 a = f00[c4], b2 = f01[c4], c = f10[c4], d = f11[c4];
            float r0 = (1.f - wy) * ((1.f - wx) * a.x + wx * b2.x) + wy * ((1.f - wx) * c.x + wx * d.x);
            float r1 = (1.f - wy) * ((1.f - wx) * a.y + wx * b2.y) + wy * ((1.f - wx) * c.y + wx * d.y);
            float r2 = (1.f - wy) * ((1.f - wx) * a.z + wx * b2.z) + wy * ((1.f - wx) * c.z + wx * d.z);
            float r3 = (1.f - wy) * ((1.f - wx) * a.w + wx * b2.w) + wy * ((1.f - wx) * c.w + wx * d.w);
            uint2 hv, lv;
            hv.x = packbf(r0, r1); hv.y = packbf(r2, r3);
            lv.x = packbf(r0 - bf_hi(r0), r1 - bf_hi(r1));
            lv.y = packbf(r2 - bf_hi(r2), r3 - bf_hi(r3));
            *(uint2*)&g_Xa_hi[row + (size_t)c4 * 4] = hv;
            *(uint2*)&g_Xa_lo[row + (size_t)c4 * 4] = lv;
        }
    }
    {   // coarse residual -> cols [256..287] of Xa AND Xb (zeros past 274)
        float y = cy * 128.f - 0.5f, x = cx * 128.f - 0.5f;
        float y0f = floorf(y), x0f = floorf(x);
        float wy = y - y0f, wx = x - x0f;
        int y0 = min(max((int)y0f, 0), COH - 1);
        int y1 = min(max((int)y0f + 1, 0), COH - 1);
        int x0 = min(max((int)x0f, 0), COW - 1);
        int x1 = min(max((int)x0f + 1, 0), COW - 1);
        const float* cb = coarse + (size_t)b * COH * COW * CLS;
        int c = lane;
        float v = 0.f;
        if (c < CLS) {
            float a = cb[(y0 * COW + x0) * CLS + c];
            float b2 = cb[(y0 * COW + x1) * CLS + c];
            float cc = cb[(y1 * COW + x0) * CLS + c];
            float d = cb[(y1 * COW + x1) * CLS + c];
            v = (1.f - wy) * ((1.f - wx) * a + wx * b2) + wy * ((1.f - wx) * cc + wx * d);
        }
        __nv_bfloat16 hv = __float2bfloat16(v);
        __nv_bfloat16 lv = __float2bfloat16(v - bf_hi(v));
        size_t off = row + 256 + lane;
        g_Xa_hi[off] = hv; g_Xa_lo[off] = lv;
        g_Xb_hi[off] = hv; g_Xb_lo[off] = lv;
    }
}

// ------------------------- 5. HMMA GEMM (M128 x N256 per CTA) ---------------
// 256 CTAs (1.73 waves). 8 warps: 2 (M) x 4 (N); warp tile 64x64.
// 2-stage cp.async pipeline, per-stage: A hi/lo 2x10240 + B hi/lo 2x20480.
#define SA_HI  0
#define SA_LO  10240
#define SB_HI  20480
#define SB_LO  40960
#define STAGE  61440
#define SM_DYN 122880
#define RSTR2  528                   // epilogue staging row stride (bytes)

__global__ __launch_bounds__(256) void k_gemm_mma(
    const __nv_bfloat16* __restrict__ Xhi, const __nv_bfloat16* __restrict__ Xlo,
    const __nv_bfloat16* __restrict__ Whi, const __nv_bfloat16* __restrict__ Wlo,
    const float* __restrict__ bias,
    __nv_bfloat16* __restrict__ Yhi, __nv_bfloat16* __restrict__ Ylo) {
    extern __shared__ char smem[];
    __shared__ float sbias[256];
    uint32_t sb = smem_u32(smem);
    int tid = threadIdx.x, wid = tid >> 5, lane = tid & 31;
    int wm = wid & 1, wn = wid >> 1;           // warp grid 2 (M) x 4 (N)
    int m0 = blockIdx.x * 128;

    sbias[tid] = bias[tid];

    float acc[4][8][4];
#pragma unroll
    for (int i = 0; i < 4; i++)
#pragma unroll
        for (int j = 0; j < 8; j++)
#pragma unroll
            for (int q = 0; q < 4; q++) acc[i][j][q] = 0.f;

    int lrow = tid >> 2;          // 0..63
    int lq = tid & 3;             // 16B chunk within the 64B k-chunk row

    auto issue = [&](int c, int buf) {
        int kb = c * 32;
        uint32_t s0 = sb + buf * STAGE;
#pragma unroll
        for (int r = 0; r < 2; r++) {          // A: 128 rows
            int row = lrow + r * 64;
            size_t gA = (size_t)(m0 + row) * KP2 + kb + lq * 8;
            uint32_t soff = row * 80 + lq * 16;
            cp16(s0 + SA_HI + soff, Xhi + gA);
            cp16(s0 + SA_LO + soff, Xlo + gA);
        }
#pragma unroll
        for (int r = 0; r < 4; r++) {          // B: 256 rows
            int row = lrow + r * 64;
            size_t gB = (size_t)row * KP2 + kb + lq * 8;
            uint32_t soff = row * 80 + lq * 16;
            cp16(s0 + SB_HI + soff, Whi + gB);
            cp16(s0 + SB_LO + soff, Wlo + gB);
        }
        cp_commit();
    };

    issue(0, 0);

    for (int c = 0; c < NC; c++) {
        if (c < NC - 1) { issue(c + 1, (c + 1) & 1); cp_wait<1>(); }
        else cp_wait<0>();
        __syncthreads();
        uint32_t s0 = sb + (c & 1) * STAGE;
#pragma unroll
        for (int k16 = 0; k16 < 2; k16++) {
            uint32_t ah[4][4], al[4][4];
            int ka = k16 * 32 + ((lane >> 4) << 4);
            int kb2 = k16 * 32 + (((lane >> 3) & 1) << 4);
#pragma unroll
            for (int mt = 0; mt < 4; mt++) {
                int row = wm * 64 + mt * 16 + (lane & 15);
                uint32_t a = s0 + row * 80 + ka;
                ldsm4(ah[mt], a + SA_HI);
                ldsm4(al[mt], a + SA_LO);
            }
#pragma unroll
            for (int nt = 0; nt < 8; nt++) {
                uint32_t bh[2], bl[2];
                int n = wn * 64 + nt * 8 + (lane & 7);
                uint32_t a2 = s0 + n * 80 + kb2;
                ldsm2(bh, a2 + SB_HI);
                ldsm2(bl, a2 + SB_LO);
#pragma unroll
                for (int mt = 0; mt < 4; mt++) {
                    mma_bf16(acc[mt][nt], ah[mt], bh);
                    mma_bf16(acc[mt][nt], ah[mt], bl);
                    mma_bf16(acc[mt][nt], al[mt], bh);
                }
            }
        }
        __syncthreads();
    }

    // epilogue: bias + relu, stage in smem, coalesced uint4 stores (hi then lo)
#pragma unroll
    for (int pass = 0; pass < 2; pass++) {
        __syncthreads();
#pragma unroll
        for (int mt = 0; mt < 4; mt++)
#pragma unroll
            for (int nt = 0; nt < 8; nt++) {
                int col = wn * 64 + nt * 8 + (lane & 3) * 2;
                float bi0 = sbias[col], bi1 = sbias[col + 1];
#pragma unroll
                for (int h = 0; h < 2; h++) {
                    int row = wm * 64 + mt * 16 + (lane >> 2) + h * 8;
                    float v0 = acc[mt][nt][2 * h] + bi0;
                    float v1 = acc[mt][nt][2 * h + 1] + bi1;
                    v0 = v0 > 0.f ? v0 : 0.f;
                    v1 = v1 > 0.f ? v1 : 0.f;
                    uint32_t pv = (pass == 0)
                        ? packbf(v0, v1)
                        : packbf(v0 - bf_hi(v0), v1 - bf_hi(v1));
                    *(uint32_t*)(smem + row * RSTR2 + col * 2) = pv;
                }
            }
        __syncthreads();
        __nv_bfloat16* Y = (pass == 0) ? Yhi : Ylo;
#pragma unroll
        for (int i = 0; i < 16; i++) {
            int u = tid + i * 256;
            int row = u >> 5, q = u & 31;
            uint4 v = *(uint4*)(smem + row * RSTR2 + q * 16);
            *(uint4*)&Y[(size_t)(m0 + row) * KP2 + q * 8] = v;
        }
    }
}

// ------------------------- 6. final layer (N=19) ---------------------------
__global__ __launch_bounds__(256) void k_final(const __nv_bfloat16* __restrict__ Xhi,
                                               const __nv_bfloat16* __restrict__ Xlo,
                                               const float* __restrict__ wf,
                                               const float* __restrict__ bf,
                                               float* __restrict__ out) {
    __shared__ float swf[KDIM * CLS];
    for (int i = threadIdx.x; i < KDIM * CLS; i += 256) swf[i] = wf[i];
    __syncthreads();
    int w = (blockIdx.x * 256 + threadIdx.x) >> 5;
    int lane = threadIdx.x & 31;
    const __nv_bfloat16* xh = Xhi + (size_t)w * KP2;
    const __nv_bfloat16* xl = Xlo + (size_t)w * KP2;
    float acc[CLS];
#pragma unroll
    for (int c = 0; c < CLS; c++) acc[c] = 0.f;
    for (int k = lane; k < KDIM; k += 32) {
        float xv = __bfloat162float(xh[k]) + __bfloat162float(xl[k]);
        const float* wr = &swf[k * CLS];
#pragma unroll
        for (int c = 0; c < CLS; c++) acc[c] += xv * wr[c];
    }
#pragma unroll
    for (int off = 16; off; off >>= 1)
#pragma unroll
        for (int c = 0; c < CLS; c++) acc[c] += __shfl_xor_sync(0xffffffffu, acc[c], off);
    if (lane == 0) {
        float* o = out + (size_t)w * CLS;
#pragma unroll
        for (int c = 0; c < CLS; c++) o[c] = acc[c] + bf[c];
    }
}

// ------------------------- launch ------------------------------------------
extern "C" void kernel_launch(void* const* d_in, const int* in_sizes, int n_in, void* d_out,
                              int out_size) {
    const float* coarse = (const float*)d_in[1];
    const float* fine0 = (const float*)d_in[2];
    const float* rand_coords = (const float*)d_in[3];
    const float* rand_fill = (const float*)d_in[4];
    const float* w0 = (const float*)d_in[5];
    const float* b0 = (const float*)d_in[6];
    const float* w1 = (const float*)d_in[7];
    const float* b1 = (const float*)d_in[8];
    const float* w2 = (const float*)d_in[9];
    const float* b2 = (const float*)d_in[10];
    const float* wf = (const float*)d_in[11];
    const float* bf = (const float*)d_in[12];
    float* out = (float*)d_out;

    const size_t PROBS = (size_t)Bn * 512 * 512 * CLS;
    const size_t LOGITS = (size_t)Bn * PTR * CLS;
    float* out_probs = out;
    float* out_logits = out + PROBS;
    float* out_coords = out + PROBS + LOGITS;

    void *pXah, *pXal, *pXbh, *pXbl, *pWh, *pWl;
    cudaGetSymbolAddress(&pXah, g_Xa_hi);
    cudaGetSymbolAddress(&pXal, g_Xa_lo);
    cudaGetSymbolAddress(&pXbh, g_Xb_hi);
    cudaGetSymbolAddress(&pXbl, g_Xb_lo);
    cudaGetSymbolAddress(&pWh, g_Wt_hi);
    cudaGetSymbolAddress(&pWl, g_Wt_lo);
    __nv_bfloat16* Xah = (__nv_bfloat16*)pXah;
    __nv_bfloat16* Xal = (__nv_bfloat16*)pXal;
    __nv_bfloat16* Xbh = (__nv_bfloat16*)pXbh;
    __nv_bfloat16* Xbl = (__nv_bfloat16*)pXbl;
    __nv_bfloat16* Wh = (__nv_bfloat16*)pWh;
    __nv_bfloat16* Wl = (__nv_bfloat16*)pWl;

    cudaFuncSetAttribute(k_gemm_mma, cudaFuncAttributeMaxDynamicSharedMemorySize, SM_DYN);

    // fused setup: resize+softmax | prep_w | uncertainty (one launch)
    k_setup<<<5472, 256>>>(coarse, rand_coords, w0, w1, w2, out_probs);

    // per-batch bitonic sort: local sorts + column-merged global stages
    k_lsort<<<32, 1024>>>();
    k_colmerge<<<32, 1024>>>(8192);
    k_lmerge<<<32, 1024>>>(8192);
    k_colmerge<<<32, 1024>>>(16384);
    k_lmerge<<<32, 1024>>>(16384);
    k_colmerge<<<32, 1024>>>(32768);
    k_lmerge_top<<<8, 1024>>>();

    k_sample<<<4096, 256>>>(coarse, fine0, rand_coords, rand_fill, out_coords);

    const int WSTR = 256 * KP2;
    k_gemm_mma<<<256, 256, SM_DYN>>>(Xah, Xal, Wh, Wl, b0, Xbh, Xbl);
    k_gemm_mma<<<256, 256, SM_DYN>>>(Xbh, Xbl, Wh + WSTR, Wl + WSTR, b1, Xah, Xal);
    k_gemm_mma<<<256, 256, SM_DYN>>>(Xah, Xal, Wh + 2 * WSTR, Wl + 2 * WSTR, b2, Xbh, Xbl);
    k_final<<<4096, 256>>>(Xbh, Xbl, wf, bf, out_logits);
}

// round 16
// speedup vs baseline: 1.1482x; 1.0486x over previous
#include <cuda_runtime.h>
#include <cuda_bf16.h>
#include <math.h>
#include <stdint.h>

#define Bn    4
#define COH   128
#define COW   128
#define CLS   19
#define FIH   256
#define FIW   256
#define FIC   256
#define PTR   8192
#define POS   24576
#define NUNC  6144
#define NRAND 2048
#define NSORT 32768
#define KDIM  275
#define NH    256
#define CHUNK 4096
#define KP2   288        // padded K for tensor path (9 x 32)
#define NC    9          // K chunks
#define MTOT  32768      // Bn*PTR

// ------------------------- scratch (device globals, no allocs) -------------
__device__ unsigned long long g_keys[Bn * NSORT];
__device__ unsigned long long g_tmp[Bn * 3 * NUNC];
__device__ __align__(16) __nv_bfloat16 g_Xa_hi[(size_t)MTOT * KP2];
__device__ __align__(16) __nv_bfloat16 g_Xa_lo[(size_t)MTOT * KP2];
__device__ __align__(16) __nv_bfloat16 g_Xb_hi[(size_t)MTOT * KP2];
__device__ __align__(16) __nv_bfloat16 g_Xb_lo[(size_t)MTOT * KP2];
__device__ __align__(16) __nv_bfloat16 g_Wt_hi[3 * 256 * KP2];
__device__ __align__(16) __nv_bfloat16 g_Wt_lo[3 * 256 * KP2];

// ------------------------- small helpers -----------------------------------
__device__ __forceinline__ float lerp_rn(float w, float a, float b) {
    return __fadd_rn(__fmul_rn(__fsub_rn(1.0f, w), a), __fmul_rn(w, b));
}
__device__ __forceinline__ float bf_hi(float v) {
    return __bfloat162float(__float2bfloat16(v));
}
__device__ __forceinline__ uint32_t packbf(float e0, float e1) {
    uint32_t r;
    asm("cvt.rn.bf16x2.f32 %0, %1, %2;" : "=r"(r) : "f"(e1), "f"(e0));
    return r;
}
__device__ __forceinline__ uint32_t smem_u32(const void* p) {
    uint32_t a;
    asm("{ .reg .u64 t; cvta.to.shared.u64 t, %1; cvt.u32.u64 %0, t; }" : "=r"(a) : "l"(p));
    return a;
}
__device__ __forceinline__ void cp16(uint32_t dst, const void* src) {
    asm volatile("cp.async.cg.shared.global [%0], [%1], 16;" :: "r"(dst), "l"(src) : "memory");
}
__device__ __forceinline__ void cp_commit() {
    asm volatile("cp.async.commit_group;" ::: "memory");
}
template <int N>
__device__ __forceinline__ void cp_wait() {
    asm volatile("cp.async.wait_group %0;" :: "n"(N) : "memory");
}
__device__ __forceinline__ void ldsm4(uint32_t r[4], uint32_t addr) {
    asm volatile("ldmatrix.sync.aligned.m8n8.x4.shared.b16 {%0,%1,%2,%3}, [%4];"
                 : "=r"(r[0]), "=r"(r[1]), "=r"(r[2]), "=r"(r[3]) : "r"(addr));
}
__device__ __forceinline__ void ldsm2(uint32_t r[2], uint32_t addr) {
    asm volatile("ldmatrix.sync.aligned.m8n8.x2.shared.b16 {%0,%1}, [%2];"
                 : "=r"(r[0]), "=r"(r[1]) : "r"(addr));
}
__device__ __forceinline__ void mma_bf16(float c[4], const uint32_t a[4], const uint32_t b[2]) {
    asm volatile(
        "mma.sync.aligned.m16n8k16.row.col.f32.bf16.bf16.f32 "
        "{%0,%1,%2,%3}, {%4,%5,%6,%7}, {%8,%9}, {%0,%1,%2,%3};"
        : "+f"(c[0]), "+f"(c[1]), "+f"(c[2]), "+f"(c[3])
        : "r"(a[0]), "r"(a[1]), "r"(a[2]), "r"(a[3]), "r"(b[0]), "r"(b[1]));
}

// ------------------------- setup bodies (fused into one kernel) -------------
__device__ void body_resize_softmax(int blk, const float* __restrict__ coarse,
                                    float* __restrict__ op) {
    int t = blk * 256 + threadIdx.x;
    int b = t >> 18;
    int rem = t & 262143;
    int y = rem >> 9;
    int x = rem & 511;
    float sy = (y + 0.5f) * 0.25f - 0.5f;
    float sx = (x + 0.5f) * 0.25f - 0.5f;
    float y0f = floorf(sy), x0f = floorf(sx);
    float wy = sy - y0f, wx = sx - x0f;
    int y0 = min(max((int)y0f, 0), COH - 1);
    int y1 = min(max((int)y0f + 1, 0), COH - 1);
    int x0 = min(max((int)x0f, 0), COW - 1);
    int x1 = min(max((int)x0f + 1, 0), COW - 1);
    const float* cb = coarse + (size_t)b * COH * COW * CLS;
    const float* p00 = cb + (y0 * COW + x0) * CLS;
    const float* p01 = cb + (y0 * COW + x1) * CLS;
    const float* p10 = cb + (y1 * COW + x0) * CLS;
    const float* p11 = cb + (y1 * COW + x1) * CLS;
    float v[CLS];
    float m = -3.0e38f;
#pragma unroll
    for (int c = 0; c < CLS; c++) {
        float top = (1.f - wx) * p00[c] + wx * p01[c];
        float bot = (1.f - wx) * p10[c] + wx * p11[c];
        v[c] = (1.f - wy) * top + wy * bot;
        m = fmaxf(m, v[c]);
    }
    float s = 0.f;
#pragma unroll
    for (int c = 0; c < CLS; c++) {
        v[c] = expf(v[c] - m);
        s += v[c];
    }
    float inv = 1.f / s;
    float* o = op + (size_t)t * CLS;
#pragma unroll
    for (int c = 0; c < CLS; c++) o[c] = v[c] * inv;
}

__device__ void body_prep_w(int blk, const float* __restrict__ w0,
                            const float* __restrict__ w1, const float* __restrict__ w2) {
    int t = blk * 256 + threadIdx.x;   // 3*256*288
    if (t >= 3 * 256 * KP2) return;
    int l = t / (256 * KP2);
    int rem = t - l * 256 * KP2;
    int n = rem / KP2, k = rem - n * KP2;
    const float* W = (l == 0) ? w0 : ((l == 1) ? w1 : w2);
    int r;
    if (l == 0) r = (k < 256) ? (k + CLS) : ((k < KDIM) ? (k - 256) : -1);
    else        r = (k < KDIM) ? k : -1;
    float v = (r >= 0) ? W[(size_t)r * NH + n] : 0.f;
    float h = bf_hi(v);
    g_Wt_hi[t] = __float2bfloat16(v);
    g_Wt_lo[t] = __float2bfloat16(v - h);
}

__device__ void body_uncertainty(int blk, const float* __restrict__ coarse,
                                 const float* __restrict__ rc) {
    int t = blk * 256 + threadIdx.x;
    if (t >= Bn * POS) return;
    int b = t / POS;
    int p = t - b * POS;
    float cy = rc[((size_t)b * POS + p) * 2 + 0];
    float cx = rc[((size_t)b * POS + p) * 2 + 1];
    float y = __fadd_rn(__fmul_rn(cy, 128.f), -0.5f);
    float x = __fadd_rn(__fmul_rn(cx, 128.f), -0.5f);
    float y0f = floorf(y), x0f = floorf(x);
    float wy = __fsub_rn(y, y0f);
    float wx = __fsub_rn(x, x0f);
    int y0 = min(max((int)y0f, 0), COH - 1);
    int y1 = min(max((int)y0f + 1, 0), COH - 1);
    int x0 = min(max((int)x0f, 0), COW - 1);
    int x1 = min(max((int)x0f + 1, 0), COW - 1);
    const float* cb = coarse + (size_t)b * COH * COW * CLS;
    const float* p00 = cb + (y0 * COW + x0) * CLS;
    const float* p01 = cb + (y0 * COW + x1) * CLS;
    const float* p10 = cb + (y1 * COW + x0) * CLS;
    const float* p11 = cb + (y1 * COW + x1) * CLS;
    float m1 = -3.0e38f, m2 = -3.0e38f;
#pragma unroll
    for (int c = 0; c < CLS; c++) {
        float top = lerp_rn(wx, p00[c], p01[c]);
        float bot = lerp_rn(wx, p10[c], p11[c]);
        float v = lerp_rn(wy, top, bot);
        if (v > m1) { m2 = m1; m1 = v; }
        else if (v > m2) m2 = v;
    }
    float unc = __fsub_rn(m2, m1);
    unsigned u = __float_as_uint(unc);
    u = (u & 0x80000000u) ? ~u : (u | 0x80000000u);
    u = ~u;   // ascending ull = descending uncertainty
    g_keys[(size_t)b * NSORT + p] = ((unsigned long long)u << 32) | (unsigned)p;
}

// one launch: blocks [0,4096) resize | [4096,4960) prep_w | [4960,5344) unc
__global__ __launch_bounds__(256) void k_setup(const float* __restrict__ coarse,
                                               const float* __restrict__ rc,
                                               const float* __restrict__ w0,
                                               const float* __restrict__ w1,
                                               const float* __restrict__ w2,
                                               float* __restrict__ out_probs) {
    int blk = blockIdx.x;
    if (blk < 4096) body_resize_softmax(blk, coarse, out_probs);
    else if (blk < 4960) body_prep_w(blk - 4096, w0, w1, w2);
    else body_uncertainty(blk - 4960, coarse, rc);
}

// ------------------------- 2. local ascending sorts (6 real chunks) ---------
__global__ __launch_bounds__(1024) void k_lsort() {
    __shared__ unsigned long long s[CHUNK];
    int b = blockIdx.x / 6, ch = blockIdx.x - b * 6;
    size_t base = (size_t)b * NSORT + ch * CHUNK;
    for (int i = threadIdx.x; i < CHUNK; i += 1024) s[i] = g_keys[base + i];
    __syncthreads();
    for (int k = 2; k <= CHUNK; k <<= 1) {
        for (int j = k >> 1; j >= 64; j >>= 1) {
#pragma unroll
            for (int r = 0; r < 2; r++) {
                int t = threadIdx.x + r * 1024;
                int i = ((t & ~(j - 1)) << 1) | (t & (j - 1));
                int ixj = i + j;
                bool up = ((i & k) == 0);
                unsigned long long A = s[i], Bv = s[ixj];
                if ((A > Bv) == up) { s[i] = Bv; s[ixj] = A; }
            }
            __syncthreads();
        }
        int j0 = (k >> 1) < 32 ? (k >> 1) : 32;
        for (int j = j0; j > 0; j >>= 1) {
#pragma unroll
            for (int r = 0; r < 2; r++) {
                int t = threadIdx.x + r * 1024;
                int i = ((t & ~(j - 1)) << 1) | (t & (j - 1));
                int ixj = i + j;
                bool up = ((i & k) == 0);
                unsigned long long A = s[i], Bv = s[ixj];
                if ((A > Bv) == up) { s[i] = Bv; s[ixj] = A; }
            }
            __syncwarp();
        }
        __syncthreads();
    }
    for (int i = threadIdx.x; i < CHUNK; i += 1024) g_keys[base + i] = s[i];
}

// ------------------------- 3. merge-path top-6144 ---------------------------
// Ascending, unique keys. out[p] = (p+1)-th smallest of A union B.
__global__ __launch_bounds__(1024) void k_mergetop(int round) {
    const unsigned long long *A, *B;
    unsigned long long* out;
    int lenA, lenB;
    int p = blockIdx.x * 1024 + threadIdx.x;   // 0..6143
    if (round == 1) {
        int b = blockIdx.y / 3, m = blockIdx.y - (blockIdx.y / 3) * 3;
        A = g_keys + (size_t)b * NSORT + (size_t)(2 * m) * CHUNK;
        B = A + CHUNK;
        lenA = CHUNK; lenB = CHUNK;
        out = g_tmp + ((size_t)b * 3 + m) * NUNC;
    } else if (round == 2) {
        int b = blockIdx.y;
        A = g_tmp + (size_t)b * 3 * NUNC;
        B = A + NUNC;
        lenA = NUNC; lenB = NUNC;
        out = g_keys + (size_t)b * NSORT + 8192;
    } else {
        int b = blockIdx.y;
        A = g_keys + (size_t)b * NSORT + 8192;
        B = g_tmp + ((size_t)b * 3 + 2) * NUNC;
        lenA = NUNC; lenB = NUNC;
        out = g_keys + (size_t)b * NSORT;
    }
    int lo = p + 1 - lenB; if (lo < 0) lo = 0;
    int hi = (p + 1 < lenA) ? (p + 1) : lenA;
    while (lo < hi) {
        int mid = (lo + hi) >> 1;
        if (__ldg(&A[mid]) < __ldg(&B[p - mid])) lo = mid + 1; else hi = mid;
    }
    int a = lo, bq = p + 1 - lo;
    unsigned long long va = (a > 0) ? __ldg(&A[a - 1]) : 0ull;
    unsigned long long vb = (bq > 0) ? __ldg(&B[bq - 1]) : 0ull;
    unsigned long long r;
    if (a > 0 && bq > 0) r = va > vb ? va : vb;
    else r = (a > 0) ? va : vb;
    out[p] = r;
}

// ------------------------- 4. sampling + coords -> bf16 hi/lo ---------------
__global__ void k_sample(const float* __restrict__ coarse, const float* __restrict__ fine,
                         const float* __restrict__ rc, const float* __restrict__ rf,
                         float* __restrict__ oc) {
    int gt = blockIdx.x * 256 + threadIdx.x;
    int w = gt >> 5, lane = gt & 31;
    int b = w >> 13, p = w & (PTR - 1);
    float cy, cx;
    if (p < NUNC) {
        unsigned idx = (unsigned)(g_keys[(size_t)b * NSORT + p] & 0xffffffffu);
        cy = rc[((size_t)b * POS + idx) * 2 + 0];
        cx = rc[((size_t)b * POS + idx) * 2 + 1];
    } else {
        int q = p - NUNC;
        cy = rf[((size_t)b * NRAND + q) * 2 + 0];
        cx = rf[((size_t)b * NRAND + q) * 2 + 1];
    }
    if (lane == 0) {
        oc[(size_t)w * 2 + 0] = cy;
        oc[(size_t)w * 2 + 1] = cx;
    }
    size_t row = (size_t)w * KP2;

    {   // fine -> cols [0..255] of Xa
        float y = cy * 256.f - 0.5f, x = cx * 256.f - 0.5f;
        float y0f = floorf(y), x0f = floorf(x);
        float wy = y - y0f, wx = x - x0f;
        int y0 = min(max((int)y0f, 0), FIH - 1);
        int y1 = min(max((int)y0f + 1, 0), FIH - 1);
        int x0 = min(max((int)x0f, 0), FIW - 1);
        int x1 = min(max((int)x0f + 1, 0), FIW - 1);
        const float* fb = fine + (size_t)b * FIH * FIW * FIC;
        const float4* f00 = (const float4*)(fb + ((size_t)y0 * FIW + x0) * FIC);
        const float4* f01 = (const float4*)(fb + ((size_t)y0 * FIW + x1) * FIC);
        const float4* f10 = (const float4*)(fb + ((size_t)y1 * FIW + x0) * FIC);
        const float4* f11 = (const float4*)(fb + ((size_t)y1 * FIW + x1) * FIC);
#pragma unroll
        for (int q = 0; q < 2; q++) {
            int c4 = lane + 32 * q;
            float4 a = f00[c4], b2 = f01[c4], c = f10[c4], d = f11[c4];
            float r0 = (1.f - wy) * ((1.f - wx) * a.x + wx * b2.x) + wy * ((1.f - wx) * c.x + wx * d.x);
            float r1 = (1.f - wy) * ((1.f - wx) * a.y + wx * b2.y) + wy * ((1.f - wx) * c.y + wx * d.y);
            float r2 = (1.f - wy) * ((1.f - wx) * a.z + wx * b2.z) + wy * ((1.f - wx) * c.z + wx * d.z);
            float r3 = (1.f - wy) * ((1.f - wx) * a.w + wx * b2.w) + wy * ((1.f - wx) * c.w + wx * d.w);
            uint2 hv, lv;
            hv.x = packbf(r0, r1); hv.y = packbf(r2, r3);
            lv.x = packbf(r0 - bf_hi(r0), r1 - bf_hi(r1));
            lv.y = packbf(r2 - bf_hi(r2), r3 - bf_hi(r3));
            *(uint2*)&g_Xa_hi[row + (size_t)c4 * 4] = hv;
            *(uint2*)&g_Xa_lo[row + (size_t)c4 * 4] = lv;
        }
    }
    {   // coarse residual -> cols [256..287] of Xa AND Xb (zeros past 274)
        float y = cy * 128.f - 0.5f, x = cx * 128.f - 0.5f;
        float y0f = floorf(y), x0f = floorf(x);
        float wy = y - y0f, wx = x - x0f;
        int y0 = min(max((int)y0f, 0), COH - 1);
        int y1 = min(max((int)y0f + 1, 0), COH - 1);
        int x0 = min(max((int)x0f, 0), COW - 1);
        int x1 = min(max((int)x0f + 1, 0), COW - 1);
        const float* cb = coarse + (size_t)b * COH * COW * CLS;
        int c = lane;
        float v = 0.f;
        if (c < CLS) {
            float a = cb[(y0 * COW + x0) * CLS + c];
            float b2 = cb[(y0 * COW + x1) * CLS + c];
            float cc = cb[(y1 * COW + x0) * CLS + c];
            float d = cb[(y1 * COW + x1) * CLS + c];
            v = (1.f - wy) * ((1.f - wx) * a + wx * b2) + wy * ((1.f - wx) * cc + wx * d);
        }
        __nv_bfloat16 hv = __float2bfloat16(v);
        __nv_bfloat16 lv = __float2bfloat16(v - bf_hi(v));
        size_t off = row + 256 + lane;
        g_Xa_hi[off] = hv; g_Xa_lo[off] = lv;
        g_Xb_hi[off] = hv; g_Xb_lo[off] = lv;
    }
}

// ------------------------- 5. HMMA GEMM (M128 x N256 per CTA) ---------------
#define SA_HI  0
#define SA_LO  10240
#define SB_HI  20480
#define SB_LO  40960
#define STAGE  61440
#define SM_DYN 122880
#define RSTR2  528                   // epilogue staging row stride (bytes)

__global__ __launch_bounds__(256) void k_gemm_mma(
    const __nv_bfloat16* __restrict__ Xhi, const __nv_bfloat16* __restrict__ Xlo,
    const __nv_bfloat16* __restrict__ Whi, const __nv_bfloat16* __restrict__ Wlo,
    const float* __restrict__ bias,
    __nv_bfloat16* __restrict__ Yhi, __nv_bfloat16* __restrict__ Ylo) {
    extern __shared__ char smem[];
    __shared__ float sbias[256];
    uint32_t sb = smem_u32(smem);
    int tid = threadIdx.x, wid = tid >> 5, lane = tid & 31;
    int wm = wid & 1, wn = wid >> 1;           // warp grid 2 (M) x 4 (N)
    int m0 = blockIdx.x * 128;

    sbias[tid] = bias[tid];

    float acc[4][8][4];
#pragma unroll
    for (int i = 0; i < 4; i++)
#pragma unroll
        for (int j = 0; j < 8; j++)
#pragma unroll
            for (int q = 0; q < 4; q++) acc[i][j][q] = 0.f;

    int lrow = tid >> 2;          // 0..63
    int lq = tid & 3;             // 16B chunk within the 64B k-chunk row

    auto issue = [&](int c, int buf) {
        int kb = c * 32;
        uint32_t s0 = sb + buf * STAGE;
#pragma unroll
        for (int r = 0; r < 2; r++) {          // A: 128 rows
            int row = lrow + r * 64;
            size_t gA = (size_t)(m0 + row) * KP2 + kb + lq * 8;
            uint32_t soff = row * 80 + lq * 16;
            cp16(s0 + SA_HI + soff, Xhi + gA);
            cp16(s0 + SA_LO + soff, Xlo + gA);
        }
#pragma unroll
        for (int r = 0; r < 4; r++) {          // B: 256 rows
            int row = lrow + r * 64;
            size_t gB = (size_t)row * KP2 + kb + lq * 8;
            uint32_t soff = row * 80 + lq * 16;
            cp16(s0 + SB_HI + soff, Whi + gB);
            cp16(s0 + SB_LO + soff, Wlo + gB);
        }
        cp_commit();
    };

    issue(0, 0);

    for (int c = 0; c < NC; c++) {
        if (c < NC - 1) { issue(c + 1, (c + 1) & 1); cp_wait<1>(); }
        else cp_wait<0>();
        __syncthreads();
        uint32_t s0 = sb + (c & 1) * STAGE;
#pragma unroll
        for (int k16 = 0; k16 < 2; k16++) {
            uint32_t ah[4][4], al[4][4];
            int ka = k16 * 32 + ((lane >> 4) << 4);
            int kb2 = k16 * 32 + (((lane >> 3) & 1) << 4);
#pragma unroll
            for (int mt = 0; mt < 4; mt++) {
                int row = wm * 64 + mt * 16 + (lane & 15);
                uint32_t a = s0 + row * 80 + ka;
                ldsm4(ah[mt], a + SA_HI);
                ldsm4(al[mt], a + SA_LO);
            }
#pragma unroll
            for (int nt = 0; nt < 8; nt++) {
                uint32_t bh[2], bl[2];
                int n = wn * 64 + nt * 8 + (lane & 7);
                uint32_t a2 = s0 + n * 80 + kb2;
                ldsm2(bh, a2 + SB_HI);
                ldsm2(bl, a2 + SB_LO);
#pragma unroll
                for (int mt = 0; mt < 4; mt++) {
                    mma_bf16(acc[mt][nt], ah[mt], bh);
                    mma_bf16(acc[mt][nt], ah[mt], bl);
                    mma_bf16(acc[mt][nt], al[mt], bh);
                }
            }
        }
        __syncthreads();
    }

    // epilogue: bias + relu, stage in smem, coalesced uint4 stores (hi then lo)
#pragma unroll
    for (int pass = 0; pass < 2; pass++) {
        __syncthreads();
#pragma unroll
        for (int mt = 0; mt < 4; mt++)
#pragma unroll
            for (int nt = 0; nt < 8; nt++) {
                int col = wn * 64 + nt * 8 + (lane & 3) * 2;
                float bi0 = sbias[col], bi1 = sbias[col + 1];
#pragma unroll
                for (int h = 0; h < 2; h++) {
                    int row = wm * 64 + mt * 16 + (lane >> 2) + h * 8;
                    float v0 = acc[mt][nt][2 * h] + bi0;
                    float v1 = acc[mt][nt][2 * h + 1] + bi1;
                    v0 = v0 > 0.f ? v0 : 0.f;
                    v1 = v1 > 0.f ? v1 : 0.f;
                    uint32_t pv = (pass == 0)
                        ? packbf(v0, v1)
                        : packbf(v0 - bf_hi(v0), v1 - bf_hi(v1));
                    *(uint32_t*)(smem + row * RSTR2 + col * 2) = pv;
                }
            }
        __syncthreads();
        __nv_bfloat16* Y = (pass == 0) ? Yhi : Ylo;
#pragma unroll
        for (int i = 0; i < 16; i++) {
            int u = tid + i * 256;
            int row = u >> 5, q = u & 31;
            uint4 v = *(uint4*)(smem + row * RSTR2 + q * 16);
            *(uint4*)&Y[(size_t)(m0 + row) * KP2 + q * 8] = v;
        }
    }
}

// ------------------------- 6. final layer (N=19) ---------------------------
__global__ __launch_bounds__(256) void k_final(const __nv_bfloat16* __restrict__ Xhi,
                                               const __nv_bfloat16* __restrict__ Xlo,
                                               const float* __restrict__ wf,
                                               const float* __restrict__ bf,
                                               float* __restrict__ out) {
    __shared__ float swf[KDIM * CLS];
    for (int i = threadIdx.x; i < KDIM * CLS; i += 256) swf[i] = wf[i];
    __syncthreads();
    int w = (blockIdx.x * 256 + threadIdx.x) >> 5;
    int lane = threadIdx.x & 31;
    const __nv_bfloat16* xh = Xhi + (size_t)w * KP2;
    const __nv_bfloat16* xl = Xlo + (size_t)w * KP2;
    float acc[CLS];
#pragma unroll
    for (int c = 0; c < CLS; c++) acc[c] = 0.f;
    for (int k = lane; k < KDIM; k += 32) {
        float xv = __bfloat162float(xh[k]) + __bfloat162float(xl[k]);
        const float* wr = &swf[k * CLS];
#pragma unroll
        for (int c = 0; c < CLS; c++) acc[c] += xv * wr[c];
    }
#pragma unroll
    for (int off = 16; off; off >>= 1)
#pragma unroll
        for (int c = 0; c < CLS; c++) acc[c] += __shfl_xor_sync(0xffffffffu, acc[c], off);
    if (lane == 0) {
        float* o = out + (size_t)w * CLS;
#pragma unroll
        for (int c = 0; c < CLS; c++) o[c] = acc[c] + bf[c];
    }
}

// ------------------------- launch ------------------------------------------
extern "C" void kernel_launch(void* const* d_in, const int* in_sizes, int n_in, void* d_out,
                              int out_size) {
    const float* coarse = (const float*)d_in[1];
    const float* fine0 = (const float*)d_in[2];
    const float* rand_coords = (const float*)d_in[3];
    const float* rand_fill = (const float*)d_in[4];
    const float* w0 = (const float*)d_in[5];
    const float* b0 = (const float*)d_in[6];
    const float* w1 = (const float*)d_in[7];
    const float* b1 = (const float*)d_in[8];
    const float* w2 = (const float*)d_in[9];
    const float* b2 = (const float*)d_in[10];
    const float* wf = (const float*)d_in[11];
    const float* bf = (const float*)d_in[12];
    float* out = (float*)d_out;

    const size_t PROBS = (size_t)Bn * 512 * 512 * CLS;
    const size_t LOGITS = (size_t)Bn * PTR * CLS;
    float* out_probs = out;
    float* out_logits = out + PROBS;
    float* out_coords = out + PROBS + LOGITS;

    void *pXah, *pXal, *pXbh, *pXbl, *pWh, *pWl;
    cudaGetSymbolAddress(&pXah, g_Xa_hi);
    cudaGetSymbolAddress(&pXal, g_Xa_lo);
    cudaGetSymbolAddress(&pXbh, g_Xb_hi);
    cudaGetSymbolAddress(&pXbl, g_Xb_lo);
    cudaGetSymbolAddress(&pWh, g_Wt_hi);
    cudaGetSymbolAddress(&pWl, g_Wt_lo);
    __nv_bfloat16* Xah = (__nv_bfloat16*)pXah;
    __nv_bfloat16* Xal = (__nv_bfloat16*)pXal;
    __nv_bfloat16* Xbh = (__nv_bfloat16*)pXbh;
    __nv_bfloat16* Xbl = (__nv_bfloat16*)pXbl;
    __nv_bfloat16* Wh = (__nv_bfloat16*)pWh;
    __nv_bfloat16* Wl = (__nv_bfloat16*)pWl;

    cudaFuncSetAttribute(k_gemm_mma, cudaFuncAttributeMaxDynamicSharedMemorySize, SM_DYN);

    // fused setup: resize+softmax | prep_w | uncertainty (one launch)
    k_setup<<<5344, 256>>>(coarse, rand_coords, w0, w1, w2, out_probs);

    // top-6144 selection: 6 local ascending sorts + 3 merge-path rounds
    k_lsort<<<24, 1024>>>();
    k_mergetop<<<dim3(6, 12), 1024>>>(1);
    k_mergetop<<<dim3(6, 4), 1024>>>(2);
    k_mergetop<<<dim3(6, 4), 1024>>>(3);

    k_sample<<<4096, 256>>>(coarse, fine0, rand_coords, rand_fill, out_coords);

    const int WSTR = 256 * KP2;
    k_gemm_mma<<<256, 256, SM_DYN>>>(Xah, Xal, Wh, Wl, b0, Xbh, Xbl);
    k_gemm_mma<<<256, 256, SM_DYN>>>(Xbh, Xbl, Wh + WSTR, Wl + WSTR, b1, Xah, Xal);
    k_gemm_mma<<<256, 256, SM_DYN>>>(Xah, Xal, Wh + 2 * WSTR, Wl + 2 * WSTR, b2, Xbh, Xbl);
    k_final<<<4096, 256>>>(Xbh, Xbl, wf, bf, out_logits);
}

// round 17
// speedup vs baseline: 1.1980x; 1.0434x over previous
#include <cuda_runtime.h>
#include <cuda_bf16.h>
#include <math.h>
#include <stdint.h>

#define Bn    4
#define COH   128
#define COW   128
#define CLS   19
#define FIH   256
#define FIW   256
#define FIC   256
#define PTR   8192
#define POS   24576
#define NUNC  6144
#define NRAND 2048
#define NSORT 32768
#define KDIM  275
#define NH    256
#define LCH   2048       // local sort chunk
#define KP2   288        // padded K for tensor path (9 x 32)
#define NC    9          // K chunks
#define MTOT  32768      // Bn*PTR

// ------------------------- scratch (device globals, no allocs) -------------
__device__ unsigned long long g_keys[Bn * NSORT];
__device__ unsigned long long g_mrg[Bn * 6 * 4096];
__device__ unsigned long long g_tmp[Bn * 3 * NUNC];
__device__ __align__(16) __nv_bfloat16 g_Xa_hi[(size_t)MTOT * KP2];
__device__ __align__(16) __nv_bfloat16 g_Xa_lo[(size_t)MTOT * KP2];
__device__ __align__(16) __nv_bfloat16 g_Xb_hi[(size_t)MTOT * KP2];
__device__ __align__(16) __nv_bfloat16 g_Xb_lo[(size_t)MTOT * KP2];
__device__ __align__(16) __nv_bfloat16 g_Wt_hi[3 * 256 * KP2];
__device__ __align__(16) __nv_bfloat16 g_Wt_lo[3 * 256 * KP2];

// ------------------------- small helpers -----------------------------------
__device__ __forceinline__ float lerp_rn(float w, float a, float b) {
    return __fadd_rn(__fmul_rn(__fsub_rn(1.0f, w), a), __fmul_rn(w, b));
}
__device__ __forceinline__ float bf_hi(float v) {
    return __bfloat162float(__float2bfloat16(v));
}
__device__ __forceinline__ uint32_t packbf(float e0, float e1) {
    uint32_t r;
    asm("cvt.rn.bf16x2.f32 %0, %1, %2;" : "=r"(r) : "f"(e1), "f"(e0));
    return r;
}
__device__ __forceinline__ uint32_t smem_u32(const void* p) {
    uint32_t a;
    asm("{ .reg .u64 t; cvta.to.shared.u64 t, %1; cvt.u32.u64 %0, t; }" : "=r"(a) : "l"(p));
    return a;
}
__device__ __forceinline__ void cp16(uint32_t dst, const void* src) {
    asm volatile("cp.async.cg.shared.global [%0], [%1], 16;" :: "r"(dst), "l"(src) : "memory");
}
__device__ __forceinline__ void cp_commit() {
    asm volatile("cp.async.commit_group;" ::: "memory");
}
template <int N>
__device__ __forceinline__ void cp_wait() {
    asm volatile("cp.async.wait_group %0;" :: "n"(N) : "memory");
}
__device__ __forceinline__ void ldsm4(uint32_t r[4], uint32_t addr) {
    asm volatile("ldmatrix.sync.aligned.m8n8.x4.shared.b16 {%0,%1,%2,%3}, [%4];"
                 : "=r"(r[0]), "=r"(r[1]), "=r"(r[2]), "=r"(r[3]) : "r"(addr));
}
__device__ __forceinline__ void ldsm2(uint32_t r[2], uint32_t addr) {
    asm volatile("ldmatrix.sync.aligned.m8n8.x2.shared.b16 {%0,%1}, [%2];"
                 : "=r"(r[0]), "=r"(r[1]) : "r"(addr));
}
__device__ __forceinline__ void mma_bf16(float c[4], const uint32_t a[4], const uint32_t b[2]) {
    asm volatile(
        "mma.sync.aligned.m16n8k16.row.col.f32.bf16.bf16.f32 "
        "{%0,%1,%2,%3}, {%4,%5,%6,%7}, {%8,%9}, {%0,%1,%2,%3};"
        : "+f"(c[0]), "+f"(c[1]), "+f"(c[2]), "+f"(c[3])
        : "r"(a[0]), "r"(a[1]), "r"(a[2]), "r"(a[3]), "r"(b[0]), "r"(b[1]));
}

// ------------------------- setup bodies (fused into one kernel) -------------
__device__ void body_resize_softmax(int blk, const float* __restrict__ coarse,
                                    float* __restrict__ op) {
    int t = blk * 256 + threadIdx.x;
    int b = t >> 18;
    int rem = t & 262143;
    int y = rem >> 9;
    int x = rem & 511;
    float sy = (y + 0.5f) * 0.25f - 0.5f;
    float sx = (x + 0.5f) * 0.25f - 0.5f;
    float y0f = floorf(sy), x0f = floorf(sx);
    float wy = sy - y0f, wx = sx - x0f;
    int y0 = min(max((int)y0f, 0), COH - 1);
    int y1 = min(max((int)y0f + 1, 0), COH - 1);
    int x0 = min(max((int)x0f, 0), COW - 1);
    int x1 = min(max((int)x0f + 1, 0), COW - 1);
    const float* cb = coarse + (size_t)b * COH * COW * CLS;
    const float* p00 = cb + (y0 * COW + x0) * CLS;
    const float* p01 = cb + (y0 * COW + x1) * CLS;
    const float* p10 = cb + (y1 * COW + x0) * CLS;
    const float* p11 = cb + (y1 * COW + x1) * CLS;
    float v[CLS];
    float m = -3.0e38f;
#pragma unroll
    for (int c = 0; c < CLS; c++) {
        float top = (1.f - wx) * p00[c] + wx * p01[c];
        float bot = (1.f - wx) * p10[c] + wx * p11[c];
        v[c] = (1.f - wy) * top + wy * bot;
        m = fmaxf(m, v[c]);
    }
    float s = 0.f;
#pragma unroll
    for (int c = 0; c < CLS; c++) {
        v[c] = expf(v[c] - m);
        s += v[c];
    }
    float inv = 1.f / s;
    float* o = op + (size_t)t * CLS;
#pragma unroll
    for (int c = 0; c < CLS; c++) o[c] = v[c] * inv;
}

__device__ void body_prep_w(int blk, const float* __restrict__ w0,
                            const float* __restrict__ w1, const float* __restrict__ w2) {
    int t = blk * 256 + threadIdx.x;   // 3*256*288
    if (t >= 3 * 256 * KP2) return;
    int l = t / (256 * KP2);
    int rem = t - l * 256 * KP2;
    int n = rem / KP2, k = rem - n * KP2;
    const float* W = (l == 0) ? w0 : ((l == 1) ? w1 : w2);
    int r;
    if (l == 0) r = (k < 256) ? (k + CLS) : ((k < KDIM) ? (k - 256) : -1);
    else        r = (k < KDIM) ? k : -1;
    float v = (r >= 0) ? W[(size_t)r * NH + n] : 0.f;
    float h = bf_hi(v);
    g_Wt_hi[t] = __float2bfloat16(v);
    g_Wt_lo[t] = __float2bfloat16(v - h);
}

__device__ void body_uncertainty(int blk, const float* __restrict__ coarse,
                                 const float* __restrict__ rc) {
    int t = blk * 256 + threadIdx.x;
    if (t >= Bn * POS) return;
    int b = t / POS;
    int p = t - b * POS;
    float cy = rc[((size_t)b * POS + p) * 2 + 0];
    float cx = rc[((size_t)b * POS + p) * 2 + 1];
    float y = __fadd_rn(__fmul_rn(cy, 128.f), -0.5f);
    float x = __fadd_rn(__fmul_rn(cx, 128.f), -0.5f);
    float y0f = floorf(y), x0f = floorf(x);
    float wy = __fsub_rn(y, y0f);
    float wx = __fsub_rn(x, x0f);
    int y0 = min(max((int)y0f, 0), COH - 1);
    int y1 = min(max((int)y0f + 1, 0), COH - 1);
    int x0 = min(max((int)x0f, 0), COW - 1);
    int x1 = min(max((int)x0f + 1, 0), COW - 1);
    const float* cb = coarse + (size_t)b * COH * COW * CLS;
    const float* p00 = cb + (y0 * COW + x0) * CLS;
    const float* p01 = cb + (y0 * COW + x1) * CLS;
    const float* p10 = cb + (y1 * COW + x0) * CLS;
    const float* p11 = cb + (y1 * COW + x1) * CLS;
    float m1 = -3.0e38f, m2 = -3.0e38f;
#pragma unroll
    for (int c = 0; c < CLS; c++) {
        float top = lerp_rn(wx, p00[c], p01[c]);
        float bot = lerp_rn(wx, p10[c], p11[c]);
        float v = lerp_rn(wy, top, bot);
        if (v > m1) { m2 = m1; m1 = v; }
        else if (v > m2) m2 = v;
    }
    float unc = __fsub_rn(m2, m1);
    unsigned u = __float_as_uint(unc);
    u = (u & 0x80000000u) ? ~u : (u | 0x80000000u);
    u = ~u;   // ascending ull = descending uncertainty
    g_keys[(size_t)b * NSORT + p] = ((unsigned long long)u << 32) | (unsigned)p;
}

// one launch: blocks [0,4096) resize | [4096,4960) prep_w | [4960,5344) unc
__global__ __launch_bounds__(256) void k_setup(const float* __restrict__ coarse,
                                               const float* __restrict__ rc,
                                               const float* __restrict__ w0,
                                               const float* __restrict__ w1,
                                               const float* __restrict__ w2,
                                               float* __restrict__ out_probs) {
    int blk = blockIdx.x;
    if (blk < 4096) body_resize_softmax(blk, coarse, out_probs);
    else if (blk < 4960) body_prep_w(blk - 4096, w0, w1, w2);
    else body_uncertainty(blk - 4960, coarse, rc);
}

// ------------------------- 2. local ascending sorts (12 x 2048 per batch) ---
__global__ __launch_bounds__(1024) void k_lsort() {
    __shared__ unsigned long long s[LCH];
    int b = blockIdx.x / 12, ch = blockIdx.x - b * 12;
    size_t base = (size_t)b * NSORT + ch * LCH;
    s[threadIdx.x] = g_keys[base + threadIdx.x];
    s[threadIdx.x + 1024] = g_keys[base + threadIdx.x + 1024];
    __syncthreads();
    for (int k = 2; k <= LCH; k <<= 1) {
        for (int j = k >> 1; j >= 64; j >>= 1) {
            int t = threadIdx.x;
            int i = ((t & ~(j - 1)) << 1) | (t & (j - 1));
            int ixj = i + j;
            bool up = ((i & k) == 0);
            unsigned long long A = s[i], Bv = s[ixj];
            if ((A > Bv) == up) { s[i] = Bv; s[ixj] = A; }
            __syncthreads();
        }
        int j0 = (k >> 1) < 32 ? (k >> 1) : 32;
        for (int j = j0; j > 0; j >>= 1) {
            int t = threadIdx.x;
            int i = ((t & ~(j - 1)) << 1) | (t & (j - 1));
            int ixj = i + j;
            bool up = ((i & k) == 0);
            unsigned long long A = s[i], Bv = s[ixj];
            if ((A > Bv) == up) { s[i] = Bv; s[ixj] = A; }
            __syncwarp();
        }
        __syncthreads();
    }
    g_keys[base + threadIdx.x] = s[threadIdx.x];
    g_keys[base + threadIdx.x + 1024] = s[threadIdx.x + 1024];
}

// ------------------------- 3. merge-path rounds ------------------------------
// Ascending, unique keys. out[p] = (p+1)-th smallest of A union B.
__global__ __launch_bounds__(1024) void k_mergetop(int round) {
    const unsigned long long *A, *B;
    unsigned long long* out;
    int lenA, lenB;
    int p = blockIdx.x * 1024 + threadIdx.x;
    if (round == 0) {          // 12 x 2048 -> 6 x 4096 (full merge)
        int b = blockIdx.y / 6, m = blockIdx.y - (blockIdx.y / 6) * 6;
        A = g_keys + (size_t)b * NSORT + (size_t)(2 * m) * LCH;
        B = A + LCH;
        lenA = LCH; lenB = LCH;
        out = g_mrg + ((size_t)b * 6 + m) * 4096;
    } else if (round == 1) {   // 6 x 4096 -> 3 x top-6144
        int b = blockIdx.y / 3, m = blockIdx.y - (blockIdx.y / 3) * 3;
        A = g_mrg + ((size_t)b * 6 + 2 * m) * 4096;
        B = A + 4096;
        lenA = 4096; lenB = 4096;
        out = g_tmp + ((size_t)b * 3 + m) * NUNC;
    } else if (round == 2) {   // T0,T1 -> top-6144
        int b = blockIdx.y;
        A = g_tmp + (size_t)b * 3 * NUNC;
        B = A + NUNC;
        lenA = NUNC; lenB = NUNC;
        out = g_keys + (size_t)b * NSORT + 8192;
    } else {                   // U,T2 -> final top-6144
        int b = blockIdx.y;
        A = g_keys + (size_t)b * NSORT + 8192;
        B = g_tmp + ((size_t)b * 3 + 2) * NUNC;
        lenA = NUNC; lenB = NUNC;
        out = g_keys + (size_t)b * NSORT;
    }
    int lo = p + 1 - lenB; if (lo < 0) lo = 0;
    int hi = (p + 1 < lenA) ? (p + 1) : lenA;
    while (lo < hi) {
        int mid = (lo + hi) >> 1;
        if (__ldg(&A[mid]) < __ldg(&B[p - mid])) lo = mid + 1; else hi = mid;
    }
    int a = lo, bq = p + 1 - lo;
    unsigned long long va = (a > 0) ? __ldg(&A[a - 1]) : 0ull;
    unsigned long long vb = (bq > 0) ? __ldg(&B[bq - 1]) : 0ull;
    unsigned long long r;
    if (a > 0 && bq > 0) r = va > vb ? va : vb;
    else r = (a > 0) ? va : vb;
    out[p] = r;
}

// ------------------------- 4. sampling + coords -> bf16 hi/lo ---------------
__global__ void k_sample(const float* __restrict__ coarse, const float* __restrict__ fine,
                         const float* __restrict__ rc, const float* __restrict__ rf,
                         float* __restrict__ oc) {
    int gt = blockIdx.x * 256 + threadIdx.x;
    int w = gt >> 5, lane = gt & 31;
    int b = w >> 13, p = w & (PTR - 1);
    float cy, cx;
    if (p < NUNC) {
        unsigned idx = (unsigned)(g_keys[(size_t)b * NSORT + p] & 0xffffffffu);
        cy = rc[((size_t)b * POS + idx) * 2 + 0];
        cx = rc[((size_t)b * POS + idx) * 2 + 1];
    } else {
        int q = p - NUNC;
        cy = rf[((size_t)b * NRAND + q) * 2 + 0];
        cx = rf[((size_t)b * NRAND + q) * 2 + 1];
    }
    if (lane == 0) {
        oc[(size_t)w * 2 + 0] = cy;
        oc[(size_t)w * 2 + 1] = cx;
    }
    size_t row = (size_t)w * KP2;

    {   // fine -> cols [0..255] of Xa
        float y = cy * 256.f - 0.5f, x = cx * 256.f - 0.5f;
        float y0f = floorf(y), x0f = floorf(x);
        float wy = y - y0f, wx = x - x0f;
        int y0 = min(max((int)y0f, 0), FIH - 1);
        int y1 = min(max((int)y0f + 1, 0), FIH - 1);
        int x0 = min(max((int)x0f, 0), FIW - 1);
        int x1 = min(max((int)x0f + 1, 0), FIW - 1);
        const float* fb = fine + (size_t)b * FIH * FIW * FIC;
        const float4* f00 = (const float4*)(fb + ((size_t)y0 * FIW + x0) * FIC);
        const float4* f01 = (const float4*)(fb + ((size_t)y0 * FIW + x1) * FIC);
        const float4* f10 = (const float4*)(fb + ((size_t)y1 * FIW + x0) * FIC);
        const float4* f11 = (const float4*)(fb + ((size_t)y1 * FIW + x1) * FIC);
#pragma unroll
        for (int q = 0; q < 2; q++) {
            int c4 = lane + 32 * q;
            float4 a = f00[c4], b2 = f01[c4], c = f10[c4], d = f11[c4];
            float r0 = (1.f - wy) * ((1.f - wx) * a.x + wx * b2.x) + wy * ((1.f - wx) * c.x + wx * d.x);
            float r1 = (1.f - wy) * ((1.f - wx) * a.y + wx * b2.y) + wy * ((1.f - wx) * c.y + wx * d.y);
            float r2 = (1.f - wy) * ((1.f - wx) * a.z + wx * b2.z) + wy * ((1.f - wx) * c.z + wx * d.z);
            float r3 = (1.f - wy) * ((1.f - wx) * a.w + wx * b2.w) + wy * ((1.f - wx) * c.w + wx * d.w);
            uint2 hv, lv;
            hv.x = packbf(r0, r1); hv.y = packbf(r2, r3);
            lv.x = packbf(r0 - bf_hi(r0), r1 - bf_hi(r1));
            lv.y = packbf(r2 - bf_hi(r2), r3 - bf_hi(r3));
            *(uint2*)&g_Xa_hi[row + (size_t)c4 * 4] = hv;
            *(uint2*)&g_Xa_lo[row + (size_t)c4 * 4] = lv;
        }
    }
    {   // coarse residual -> cols [256..287] of Xa AND Xb (zeros past 274)
        float y = cy * 128.f - 0.5f, x = cx * 128.f - 0.5f;
        float y0f = floorf(y), x0f = floorf(x);
        float wy = y - y0f, wx = x - x0f;
        int y0 = min(max((int)y0f, 0), COH - 1);
        int y1 = min(max((int)y0f + 1, 0), COH - 1);
        int x0 = min(max((int)x0f, 0), COW - 1);
        int x1 = min(max((int)x0f + 1, 0), COW - 1);
        const float* cb = coarse + (size_t)b * COH * COW * CLS;
        int c = lane;
        float v = 0.f;
        if (c < CLS) {
            float a = cb[(y0 * COW + x0) * CLS + c];
            float b2 = cb[(y0 * COW + x1) * CLS + c];
            float cc = cb[(y1 * COW + x0) * CLS + c];
            float d = cb[(y1 * COW + x1) * CLS + c];
            v = (1.f - wy) * ((1.f - wx) * a + wx * b2) + wy * ((1.f - wx) * cc + wx * d);
        }
        __nv_bfloat16 hv = __float2bfloat16(v);
        __nv_bfloat16 lv = __float2bfloat16(v - bf_hi(v));
        size_t off = row + 256 + lane;
        g_Xa_hi[off] = hv; g_Xa_lo[off] = lv;
        g_Xb_hi[off] = hv; g_Xb_lo[off] = lv;
    }
}

// ------------------------- 5. HMMA GEMM (M128 x N256 per CTA) ---------------
#define SA_HI  0
#define SA_LO  10240
#define SB_HI  20480
#define SB_LO  40960
#define STAGE  61440
#define SM_DYN 122880
#define RSTR2  528                   // epilogue staging row stride (bytes)

__global__ __launch_bounds__(256) void k_gemm_mma(
    const __nv_bfloat16* __restrict__ Xhi, const __nv_bfloat16* __restrict__ Xlo,
    const __nv_bfloat16* __restrict__ Whi, const __nv_bfloat16* __restrict__ Wlo,
    const float* __restrict__ bias,
    __nv_bfloat16* __restrict__ Yhi, __nv_bfloat16* __restrict__ Ylo) {
    extern __shared__ char smem[];
    __shared__ float sbias[256];
    uint32_t sb = smem_u32(smem);
    int tid = threadIdx.x, wid = tid >> 5, lane = tid & 31;
    int wm = wid & 1, wn = wid >> 1;           // warp grid 2 (M) x 4 (N)
    int m0 = blockIdx.x * 128;

    sbias[tid] = bias[tid];

    float acc[4][8][4];
#pragma unroll
    for (int i = 0; i < 4; i++)
#pragma unroll
        for (int j = 0; j < 8; j++)
#pragma unroll
            for (int q = 0; q < 4; q++) acc[i][j][q] = 0.f;

    int lrow = tid >> 2;          // 0..63
    int lq = tid & 3;             // 16B chunk within the 64B k-chunk row

    auto issue = [&](int c, int buf) {
        int kb = c * 32;
        uint32_t s0 = sb + buf * STAGE;
#pragma unroll
        for (int r = 0; r < 2; r++) {          // A: 128 rows
            int row = lrow + r * 64;
            size_t gA = (size_t)(m0 + row) * KP2 + kb + lq * 8;
            uint32_t soff = row * 80 + lq * 16;
            cp16(s0 + SA_HI + soff, Xhi + gA);
            cp16(s0 + SA_LO + soff, Xlo + gA);
        }
#pragma unroll
        for (int r = 0; r < 4; r++) {          // B: 256 rows
            int row = lrow + r * 64;
            size_t gB = (size_t)row * KP2 + kb + lq * 8;
            uint32_t soff = row * 80 + lq * 16;
            cp16(s0 + SB_HI + soff, Whi + gB);
            cp16(s0 + SB_LO + soff, Wlo + gB);
        }
        cp_commit();
    };

    issue(0, 0);

    for (int c = 0; c < NC; c++) {
        if (c < NC - 1) { issue(c + 1, (c + 1) & 1); cp_wait<1>(); }
        else cp_wait<0>();
        __syncthreads();
        uint32_t s0 = sb + (c & 1) * STAGE;
#pragma unroll
        for (int k16 = 0; k16 < 2; k16++) {
            uint32_t ah[4][4], al[4][4];
            int ka = k16 * 32 + ((lane >> 4) << 4);
            int kb2 = k16 * 32 + (((lane >> 3) & 1) << 4);
#pragma unroll
            for (int mt = 0; mt < 4; mt++) {
                int row = wm * 64 + mt * 16 + (lane & 15);
                uint32_t a = s0 + row * 80 + ka;
                ldsm4(ah[mt], a + SA_HI);
                ldsm4(al[mt], a + SA_LO);
            }
#pragma unroll
            for (int nt = 0; nt < 8; nt++) {
                uint32_t bh[2], bl[2];
                int n = wn * 64 + nt * 8 + (lane & 7);
                uint32_t a2 = s0 + n * 80 + kb2;
                ldsm2(bh, a2 + SB_HI);
                ldsm2(bl, a2 + SB_LO);
#pragma unroll
                for (int mt = 0; mt < 4; mt++) {
                    mma_bf16(acc[mt][nt], ah[mt], bh);
                    mma_bf16(acc[mt][nt], ah[mt], bl);
                    mma_bf16(acc[mt][nt], al[mt], bh);
                }
            }
        }
        __syncthreads();
    }

    // epilogue: bias + relu, stage in smem, coalesced uint4 stores (hi then lo)
#pragma unroll
    for (int pass = 0; pass < 2; pass++) {
        __syncthreads();
#pragma unroll
        for (int mt = 0; mt < 4; mt++)
#pragma unroll
            for (int nt = 0; nt < 8; nt++) {
                int col = wn * 64 + nt * 8 + (lane & 3) * 2;
                float bi0 = sbias[col], bi1 = sbias[col + 1];
#pragma unroll
                for (int h = 0; h < 2; h++) {
                    int row = wm * 64 + mt * 16 + (lane >> 2) + h * 8;
                    float v0 = acc[mt][nt][2 * h] + bi0;
                    float v1 = acc[mt][nt][2 * h + 1] + bi1;
                    v0 = v0 > 0.f ? v0 : 0.f;
                    v1 = v1 > 0.f ? v1 : 0.f;
                    uint32_t pv = (pass == 0)
                        ? packbf(v0, v1)
                        : packbf(v0 - bf_hi(v0), v1 - bf_hi(v1));
                    *(uint32_t*)(smem + row * RSTR2 + col * 2) = pv;
                }
            }
        __syncthreads();
        __nv_bfloat16* Y = (pass == 0) ? Yhi : Ylo;
#pragma unroll
        for (int i = 0; i < 16; i++) {
            int u = tid + i * 256;
            int row = u >> 5, q = u & 31;
            uint4 v = *(uint4*)(smem + row * RSTR2 + q * 16);
            *(uint4*)&Y[(size_t)(m0 + row) * KP2 + q * 8] = v;
        }
    }
}

// ------------------------- 6. final layer (N=19) ---------------------------
__global__ __launch_bounds__(256) void k_final(const __nv_bfloat16* __restrict__ Xhi,
                                               const __nv_bfloat16* __restrict__ Xlo,
                                               const float* __restrict__ wf,
                                               const float* __restrict__ bf,
                                               float* __restrict__ out) {
    __shared__ float swf[KDIM * CLS];
    for (int i = threadIdx.x; i < KDIM * CLS; i += 256) swf[i] = wf[i];
    __syncthreads();
    int w = (blockIdx.x * 256 + threadIdx.x) >> 5;
    int lane = threadIdx.x & 31;
    const __nv_bfloat16* xh = Xhi + (size_t)w * KP2;
    const __nv_bfloat16* xl = Xlo + (size_t)w * KP2;
    float acc[CLS];
#pragma unroll
    for (int c = 0; c < CLS; c++) acc[c] = 0.f;
    for (int k = lane; k < KDIM; k += 32) {
        float xv = __bfloat162float(xh[k]) + __bfloat162float(xl[k]);
        const float* wr = &swf[k * CLS];
#pragma unroll
        for (int c = 0; c < CLS; c++) acc[c] += xv * wr[c];
    }
#pragma unroll
    for (int off = 16; off; off >>= 1)
#pragma unroll
        for (int c = 0; c < CLS; c++) acc[c] += __shfl_xor_sync(0xffffffffu, acc[c], off);
    if (lane == 0) {
        float* o = out + (size_t)w * CLS;
#pragma unroll
        for (int c = 0; c < CLS; c++) o[c] = acc[c] + bf[c];
    }
}

// ------------------------- launch ------------------------------------------
extern "C" void kernel_launch(void* const* d_in, const int* in_sizes, int n_in, void* d_out,
                              int out_size) {
    const float* coarse = (const float*)d_in[1];
    const float* fine0 = (const float*)d_in[2];
    const float* rand_coords = (const float*)d_in[3];
    const float* rand_fill = (const float*)d_in[4];
    const float* w0 = (const float*)d_in[5];
    const float* b0 = (const float*)d_in[6];
    const float* w1 = (const float*)d_in[7];
    const float* b1 = (const float*)d_in[8];
    const float* w2 = (const float*)d_in[9];
    const float* b2 = (const float*)d_in[10];
    const float* wf = (const float*)d_in[11];
    const float* bf = (const float*)d_in[12];
    float* out = (float*)d_out;

    const size_t PROBS = (size_t)Bn * 512 * 512 * CLS;
    const size_t LOGITS = (size_t)Bn * PTR * CLS;
    float* out_probs = out;
    float* out_logits = out + PROBS;
    float* out_coords = out + PROBS + LOGITS;

    void *pXah, *pXal, *pXbh, *pXbl, *pWh, *pWl;
    cudaGetSymbolAddress(&pXah, g_Xa_hi);
    cudaGetSymbolAddress(&pXal, g_Xa_lo);
    cudaGetSymbolAddress(&pXbh, g_Xb_hi);
    cudaGetSymbolAddress(&pXbl, g_Xb_lo);
    cudaGetSymbolAddress(&pWh, g_Wt_hi);
    cudaGetSymbolAddress(&pWl, g_Wt_lo);
    __nv_bfloat16* Xah = (__nv_bfloat16*)pXah;
    __nv_bfloat16* Xal = (__nv_bfloat16*)pXal;
    __nv_bfloat16* Xbh = (__nv_bfloat16*)pXbh;
    __nv_bfloat16* Xbl = (__nv_bfloat16*)pXbl;
    __nv_bfloat16* Wh = (__nv_bfloat16*)pWh;
    __nv_bfloat16* Wl = (__nv_bfloat16*)pWl;

    cudaFuncSetAttribute(k_gemm_mma, cudaFuncAttributeMaxDynamicSharedMemorySize, SM_DYN);

    // fused setup: resize+softmax | prep_w | uncertainty (one launch)
    k_setup<<<5344, 256>>>(coarse, rand_coords, w0, w1, w2, out_probs);

    // top-6144 selection: 48 local 2048-sorts + 4 merge-path rounds
    k_lsort<<<48, 1024>>>();
    k_mergetop<<<dim3(4, 24), 1024>>>(0);
    k_mergetop<<<dim3(6, 12), 1024>>>(1);
    k_mergetop<<<dim3(6, 4), 1024>>>(2);
    k_mergetop<<<dim3(6, 4), 1024>>>(3);

    k_sample<<<4096, 256>>>(coarse, fine0, rand_coords, rand_fill, out_coords);

    const int WSTR = 256 * KP2;
    k_gemm_mma<<<256, 256, SM_DYN>>>(Xah, Xal, Wh, Wl, b0, Xbh, Xbl);
    k_gemm_mma<<<256, 256, SM_DYN>>>(Xbh, Xbl, Wh + WSTR, Wl + WSTR, b1, Xah, Xal);
    k_gemm_mma<<<256, 256, SM_DYN>>>(Xah, Xal, Wh + 2 * WSTR, Wl + 2 * WSTR, b2, Xbh, Xbl);
    k_final<<<4096, 256>>>(Xbh, Xbl, wf, bf, out_logits);
}